// round 15
// baseline (speedup 1.0000x reference)
#include <cuda_runtime.h>
#include <cuda_bf16.h>
#include <math.h>
#include <stdint.h>

#define TT 4096
#define DD 1024
#define NH 16
#define HDIM 64

// ---------------------------------------------------------------------------
// Scratch (allocation-free rule: device globals). 16B-aligned.
// GEMM operands chunk-major hi/lo interleaved, SW128-preswizzled:
//   [kc][row][32 hi bf16 | 32 lo bf16] (128B rows, kc = K/32)
// Attention: Q preswizzled rows [h][t][64] hi/lo; K/V packed per
// (head, 64-key tile) as one 32KB block: Kh|Kl|Vth|Vtl (8KB each).
// Two consecutive blocks form one 64KB 128-key stage.
// ---------------------------------------------------------------------------
__device__ __align__(16) float g_qkv[(size_t)TT * 3 * DD];   // 48 MB
__device__ __align__(16) __nv_bfloat16 g_xhl[(size_t)TT * DD * 2];
__device__ __align__(16) __nv_bfloat16 g_w1hl[(size_t)3 * DD * DD * 2];
__device__ __align__(16) __nv_bfloat16 g_w2hl[(size_t)DD * DD * 2];
__device__ __align__(16) __nv_bfloat16 g_ahl[(size_t)TT * DD * 2];
__device__ __align__(16) __nv_bfloat16 g_qph[(size_t)NH * TT * HDIM];
__device__ __align__(16) __nv_bfloat16 g_qpl[(size_t)NH * TT * HDIM];
__device__ __align__(16) __nv_bfloat16 g_kvp[(size_t)NH * (TT / 64) * 16384]; // 32MB

// ---------------------------------------------------------------------------
// PTX helpers
// ---------------------------------------------------------------------------
__device__ __forceinline__ uint32_t smem_u32(const void* p) {
    uint32_t a;
    asm("{ .reg .u64 t; cvta.to.shared.u64 t, %1; cvt.u32.u64 %0, t; }" : "=r"(a) : "l"(p));
    return a;
}
__device__ __forceinline__ void ldsm_x4(uint32_t& r0, uint32_t& r1, uint32_t& r2, uint32_t& r3,
                                        uint32_t addr) {
    asm volatile("ldmatrix.sync.aligned.m8n8.x4.shared.b16 {%0,%1,%2,%3}, [%4];"
                 : "=r"(r0), "=r"(r1), "=r"(r2), "=r"(r3) : "r"(addr));
}
__device__ __forceinline__ void mma16816(float& c0, float& c1, float& c2, float& c3,
                                         uint32_t a0, uint32_t a1, uint32_t a2, uint32_t a3,
                                         uint32_t b0, uint32_t b1) {
    asm("mma.sync.aligned.m16n8k16.row.col.f32.bf16.bf16.f32 "
        "{%0,%1,%2,%3}, {%4,%5,%6,%7}, {%8,%9}, {%0,%1,%2,%3};"
        : "+f"(c0), "+f"(c1), "+f"(c2), "+f"(c3)
        : "r"(a0), "r"(a1), "r"(a2), "r"(a3), "r"(b0), "r"(b1));
}
__device__ __forceinline__ void bulk_g2s(uint32_t dst, const void* src, uint32_t bytes,
                                         uint32_t mbar) {
    asm volatile("cp.async.bulk.shared::cluster.global.mbarrier::complete_tx::bytes "
                 "[%0], [%1], %2, [%3];"
                 :: "r"(dst), "l"(src), "r"(bytes), "r"(mbar) : "memory");
}
#define MBARRIER_INIT(mb, c) \
    asm volatile("mbarrier.init.shared.b64 [%0], %1;" :: "r"((uint32_t)(mb)), "r"((uint32_t)(c)) : "memory")
#define MBARRIER_EXPECT_TX(mb, bytes) \
    asm volatile("mbarrier.arrive.expect_tx.shared.b64 _, [%0], %1;" \
                 :: "r"((uint32_t)(mb)), "r"((uint32_t)(bytes)) : "memory")
#define MBARRIER_ARRIVE(mb) \
    asm volatile("mbarrier.arrive.shared.b64 _, [%0];" :: "r"((uint32_t)(mb)) : "memory")
#define MBARRIER_WAIT_PARITY(mb, ph) do { \
    uint32_t _m = (uint32_t)(mb), _p = (uint32_t)(ph), _d; \
    asm volatile("{ .reg .pred p; mbarrier.try_wait.parity.acquire.cta.shared::cta.b64 p, [%1], %2; " \
                 "selp.b32 %0, 1, 0, p; }" : "=r"(_d) : "r"(_m), "r"(_p) : "memory"); \
    if (!_d) { \
        asm volatile("{ .reg .pred P1; WL_%=: mbarrier.try_wait.parity.acquire.cta.shared::cta.b64 P1, [%0], %1, 0x989680; " \
                     "@P1 bra.uni WD_%=; bra.uni WL_%=; WD_%=: }" :: "r"(_m), "r"(_p) : "memory"); \
    } \
} while (0)

__device__ __forceinline__ float fast_exp2(float x) {
    float y;
    asm("ex2.approx.ftz.f32 %0, %1;" : "=f"(y) : "f"(x));
    return y;
}
__device__ __forceinline__ uint32_t pack_bf16x2(float a, float b) {
    __nv_bfloat162 t = __floats2bfloat162_rn(a, b);
    return *reinterpret_cast<uint32_t*>(&t);
}
__device__ __forceinline__ uint32_t swz(uint32_t o)  { return o ^ ((o >> 3) & 0x70); }
__device__ __forceinline__ size_t   swzs(size_t o)   { return o ^ ((o >> 3) & 0x70); }

__device__ __forceinline__ void split16(const float (&f)[16],
                                        uint4& h0, uint4& h1, uint4& l0, uint4& l1)
{
    float hh[16];
    #pragma unroll
    for (int i = 0; i < 16; i++) hh[i] = __bfloat162float(__float2bfloat16(f[i]));
    h0 = make_uint4(pack_bf16x2(hh[0], hh[1]),  pack_bf16x2(hh[2], hh[3]),
                    pack_bf16x2(hh[4], hh[5]),  pack_bf16x2(hh[6], hh[7]));
    h1 = make_uint4(pack_bf16x2(hh[8], hh[9]),  pack_bf16x2(hh[10], hh[11]),
                    pack_bf16x2(hh[12], hh[13]), pack_bf16x2(hh[14], hh[15]));
    l0 = make_uint4(pack_bf16x2(f[0]-hh[0], f[1]-hh[1]),   pack_bf16x2(f[2]-hh[2], f[3]-hh[3]),
                    pack_bf16x2(f[4]-hh[4], f[5]-hh[5]),   pack_bf16x2(f[6]-hh[6], f[7]-hh[7]));
    l1 = make_uint4(pack_bf16x2(f[8]-hh[8], f[9]-hh[9]),   pack_bf16x2(f[10]-hh[10], f[11]-hh[11]),
                    pack_bf16x2(f[12]-hh[12], f[13]-hh[13]), pack_bf16x2(f[14]-hh[14], f[15]-hh[15]));
}

// ---------------------------------------------------------------------------
// fp32 [M][K] -> chunk-major hi/lo preswizzled
// ---------------------------------------------------------------------------
__global__ void split_chunk(const float* __restrict__ s, __nv_bfloat16* __restrict__ o,
                            int M, int K)
{
    size_t i8 = ((size_t)blockIdx.x * blockDim.x + threadIdx.x) * 8;
    if (i8 >= (size_t)M * K) return;
    int m  = (int)(i8 / K);
    int k  = (int)(i8 % K);
    int kc = k >> 5, kin = k & 31;
    float4 v0 = *(const float4*)(s + i8);
    float4 v1 = *(const float4*)(s + i8 + 4);
    float f[8] = {v0.x, v0.y, v0.z, v0.w, v1.x, v1.y, v1.z, v1.w};
    float h[8];
    #pragma unroll
    for (int j = 0; j < 8; j++) h[j] = __bfloat162float(__float2bfloat16(f[j]));
    uint4 hu, lu;
    hu.x = pack_bf16x2(h[0], h[1]); hu.y = pack_bf16x2(h[2], h[3]);
    hu.z = pack_bf16x2(h[4], h[5]); hu.w = pack_bf16x2(h[6], h[7]);
    lu.x = pack_bf16x2(f[0]-h[0], f[1]-h[1]); lu.y = pack_bf16x2(f[2]-h[2], f[3]-h[3]);
    lu.z = pack_bf16x2(f[4]-h[4], f[5]-h[5]); lu.w = pack_bf16x2(f[6]-h[6], f[7]-h[7]);
    size_t rowb = ((size_t)kc * M + m) * 128;
    *(uint4*)((char*)o + swzs(rowb + (size_t)kin * 2))      = hu;
    *(uint4*)((char*)o + swzs(rowb + 64 + (size_t)kin * 2)) = lu;
}

// ---------------------------------------------------------------------------
// w[K][N] fp32 -> wT chunk-major hi/lo preswizzled
// ---------------------------------------------------------------------------
__global__ void wsplit_chunk(const float* __restrict__ w, __nv_bfloat16* __restrict__ o,
                             int K, int N)
{
    __shared__ float t[32][33];
    int n0 = blockIdx.x * 32, k0 = blockIdx.y * 32;
    int tx = threadIdx.x, ty = threadIdx.y;
    for (int j = ty; j < 32; j += 8)
        t[j][tx] = w[(size_t)(k0 + j) * N + n0 + tx];
    __syncthreads();
    float f0 = t[ty * 4 + 0][tx], f1 = t[ty * 4 + 1][tx];
    float f2 = t[ty * 4 + 2][tx], f3 = t[ty * 4 + 3][tx];
    float h0 = __bfloat162float(__float2bfloat16(f0));
    float h1 = __bfloat162float(__float2bfloat16(f1));
    float h2 = __bfloat162float(__float2bfloat16(f2));
    float h3 = __bfloat162float(__float2bfloat16(f3));
    uint2 hu, lu;
    hu.x = pack_bf16x2(h0, h1); hu.y = pack_bf16x2(h2, h3);
    lu.x = pack_bf16x2(f0 - h0, f1 - h1); lu.y = pack_bf16x2(f2 - h2, f3 - h3);
    size_t rowb = ((size_t)blockIdx.y * N + n0 + tx) * 128;
    *(uint2*)((char*)o + swzs(rowb + (size_t)ty * 8))      = hu;
    *(uint2*)((char*)o + swzs(rowb + 64 + (size_t)ty * 8)) = lu;
}

// ---------------------------------------------------------------------------
// kv_pack: qkv fp32 -> Q preswizzled rows (scaled, hi/lo) + 32KB K/V blocks.
// ---------------------------------------------------------------------------
__global__ __launch_bounds__(256) void kv_pack(
    const float* __restrict__ qkv,
    __nv_bfloat16* __restrict__ qph, __nv_bfloat16* __restrict__ qpl,
    __nv_bfloat16* __restrict__ kvp)
{
    __shared__ float sv[64][68];
    const int nt = blockIdx.x, h = blockIdx.y;
    const int k0 = nt * 64;
    const int tid = threadIdx.x;
    const int r  = tid >> 2;
    const int d0 = (tid & 3) * 16;
    const float sc = 0.125f * 1.4426950408889634f;

    const float* rowp = qkv + (size_t)(k0 + r) * (3 * DD) + h * HDIM + d0;
    float qf[16], kf[16];
    #pragma unroll
    for (int i = 0; i < 4; i++) {
        float4 q = *(const float4*)(rowp + 4 * i);
        float4 k = *(const float4*)(rowp + DD + 4 * i);
        float4 v = *(const float4*)(rowp + 2 * DD + 4 * i);
        qf[4*i+0] = q.x * sc; qf[4*i+1] = q.y * sc; qf[4*i+2] = q.z * sc; qf[4*i+3] = q.w * sc;
        kf[4*i+0] = k.x; kf[4*i+1] = k.y; kf[4*i+2] = k.z; kf[4*i+3] = k.w;
        sv[r][d0 + 4*i + 0] = v.x; sv[r][d0 + 4*i + 1] = v.y;
        sv[r][d0 + 4*i + 2] = v.z; sv[r][d0 + 4*i + 3] = v.w;
    }

    uint4 h0, h1, l0, l1;
    split16(qf, h0, h1, l0, l1);
    size_t qrow = ((size_t)h * TT + k0 + r) * 128;
    *(uint4*)((char*)qph + swzs(qrow + (size_t)d0 * 2))      = h0;
    *(uint4*)((char*)qph + swzs(qrow + (size_t)d0 * 2 + 16)) = h1;
    *(uint4*)((char*)qpl + swzs(qrow + (size_t)d0 * 2))      = l0;
    *(uint4*)((char*)qpl + swzs(qrow + (size_t)d0 * 2 + 16)) = l1;
    split16(kf, h0, h1, l0, l1);
    size_t kvb = (size_t)(h * (TT / 64) + nt) * 32768;
    size_t kr = (size_t)r * 128 + (size_t)d0 * 2;
    *(uint4*)((char*)kvp + kvb + swzs(kr))             = h0;
    *(uint4*)((char*)kvp + kvb + swzs(kr + 16))        = h1;
    *(uint4*)((char*)kvp + kvb + 8192 + swzs(kr))      = l0;
    *(uint4*)((char*)kvp + kvb + 8192 + swzs(kr + 16)) = l1;

    __syncthreads();
    {
        const int d  = tid >> 2;
        const int c0 = (tid & 3) * 16;
        float vf[16];
        #pragma unroll
        for (int i = 0; i < 16; i++) vf[i] = sv[c0 + i][d];
        split16(vf, h0, h1, l0, l1);
        size_t vr = (size_t)d * 128 + (size_t)c0 * 2;
        *(uint4*)((char*)kvp + kvb + 16384 + swzs(vr))      = h0;
        *(uint4*)((char*)kvp + kvb + 16384 + swzs(vr + 16)) = h1;
        *(uint4*)((char*)kvp + kvb + 24576 + swzs(vr))      = l0;
        *(uint4*)((char*)kvp + kvb + 24576 + swzs(vr + 16)) = l1;
    }
}

// ---------------------------------------------------------------------------
// mma.sync bf16 split GEMM, 2-stage bulk pipeline, warp-grained stage release.
// __syncthreads-per-chunk replaced by per-stage EMPTY mbarriers (count=8):
// each warp arrives after its last read of the stage; only tid0 waits before
// re-issuing the stage. Fast warps roll into the next chunk immediately.
// A warp cannot reach chunk t+2 before the producer's empty-wait completes,
// so arrivals cannot bleed across phases (one-phase-deep everywhere).
// ---------------------------------------------------------------------------
#define CH_BYTES 16384
#define STG_BYTES (2 * CH_BYTES)
#define GSMEM (2 * STG_BYTES)        // 65536

__global__ __launch_bounds__(256, 2) void tc_gemm(
    const __nv_bfloat16* __restrict__ Ahl, const __nv_bfloat16* __restrict__ Bhl,
    float* __restrict__ C, int M, int N, int K)
{
    extern __shared__ __align__(1024) char dsm[];
    __shared__ __align__(8) uint64_t mbar_s[4];   // full0, full1, empty0, empty1
    const uint32_t base = smem_u32(dsm);

    const int tid  = threadIdx.x;
    const int wid  = tid >> 5;
    const int lane = tid & 31;
    const int wm   = wid >> 2;
    const int wn   = wid & 3;
    const int bm   = blockIdx.y * 128, bn = blockIdx.x * 128;
    const int lrow = (lane & 7) + ((lane >> 3) & 1) * 8;
    const int lkof = (lane >> 4) * 8;

    if (tid == 0) {
        MBARRIER_INIT(smem_u32(&mbar_s[0]), 1);
        MBARRIER_INIT(smem_u32(&mbar_s[1]), 1);
        MBARRIER_INIT(smem_u32(&mbar_s[2]), 8);   // empty: one arrive per warp
        MBARRIER_INIT(smem_u32(&mbar_s[3]), 8);
    }
    __syncthreads();
    uint32_t mb0 = smem_u32(&mbar_s[0]);
    uint32_t mb1 = smem_u32(&mbar_s[1]);
    uint32_t me0 = smem_u32(&mbar_s[2]);
    uint32_t me1 = smem_u32(&mbar_s[3]);

    const int NCH = K / 32;

    auto issue = [&](int s, int t) {
        uint32_t m = s ? mb1 : mb0;
        MBARRIER_EXPECT_TX(m, STG_BYTES);
        const char* srcA = (const char*)Ahl + ((size_t)t * M + bm) * 128;
        const char* srcB = (const char*)Bhl + ((size_t)t * N + bn) * 128;
        uint32_t d = base + s * STG_BYTES;
        bulk_g2s(d,            srcA, CH_BYTES, m);
        bulk_g2s(d + CH_BYTES, srcB, CH_BYTES, m);
    };
    if (tid == 0) {
        issue(0, 0);
        if (NCH > 1) issue(1, 1);
    }

    float acc[4][4][4];
    #pragma unroll
    for (int mt = 0; mt < 4; mt++)
        #pragma unroll
        for (int nt = 0; nt < 4; nt++)
            #pragma unroll
            for (int c = 0; c < 4; c++) acc[mt][nt][c] = 0.f;

    int ph0 = 0, ph1 = 0;        // full-barrier phases (per thread)
    int eph0 = 0, eph1 = 0;      // empty-barrier phases (used by tid0 only)

    for (int t = 0; t < NCH; t++) {
        int s = t & 1;
        if (s == 0) { MBARRIER_WAIT_PARITY(mb0, ph0); ph0 ^= 1; }
        else        { MBARRIER_WAIT_PARITY(mb1, ph1); ph1 ^= 1; }

        uint32_t aB = base + s * STG_BYTES;
        uint32_t bB = aB + CH_BYTES;

        #pragma unroll
        for (int ks = 0; ks < 2; ks++) {
            const uint32_t kb = (uint32_t)(ks * 16 + lkof) * 2;

            uint32_t bh[4][2], bl[4][2];
            #pragma unroll
            for (int p = 0; p < 2; p++) {
                uint32_t ro = (uint32_t)(wn * 32 + p * 16 + lrow) * 128;
                uint32_t r0, r1, r2, r3;
                ldsm_x4(r0, r1, r2, r3, bB + swz(ro + kb));
                bh[p * 2][0] = r0; bh[p * 2][1] = r2;
                bh[p * 2 + 1][0] = r1; bh[p * 2 + 1][1] = r3;
                ldsm_x4(r0, r1, r2, r3, bB + swz(ro + 64 + kb));
                bl[p * 2][0] = r0; bl[p * 2][1] = r2;
                bl[p * 2 + 1][0] = r1; bl[p * 2 + 1][1] = r3;
            }

            #pragma unroll
            for (int mt = 0; mt < 4; mt++) {
                uint32_t ro = (uint32_t)(wm * 64 + mt * 16 + lrow) * 128;
                uint32_t ah0, ah1, ah2, ah3, al0, al1, al2, al3;
                ldsm_x4(ah0, ah1, ah2, ah3, aB + swz(ro + kb));
                ldsm_x4(al0, al1, al2, al3, aB + swz(ro + 64 + kb));
                #pragma unroll
                for (int nt = 0; nt < 4; nt++) {
                    float* c = acc[mt][nt];
                    mma16816(c[0], c[1], c[2], c[3], ah0, ah1, ah2, ah3,
                             bh[nt][0], bh[nt][1]);
                    mma16816(c[0], c[1], c[2], c[3], ah0, ah1, ah2, ah3,
                             bl[nt][0], bl[nt][1]);
                    mma16816(c[0], c[1], c[2], c[3], al0, al1, al2, al3,
                             bh[nt][0], bh[nt][1]);
                }
            }
        }
        // warp is done reading stage s (all ldsm issued & consumed into regs)
        if (lane == 0) MBARRIER_ARRIVE(s == 0 ? me0 : me1);
        // producer: wait until all 8 warps released stage s, then re-issue it
        if (tid == 0 && t + 2 < NCH) {
            if (s == 0) { MBARRIER_WAIT_PARITY(me0, eph0); eph0 ^= 1; }
            else        { MBARRIER_WAIT_PARITY(me1, eph1); eph1 ^= 1; }
            issue(s, t + 2);
        }
    }

    const int g  = lane >> 2;
    const int tg = lane & 3;
    #pragma unroll
    for (int mt = 0; mt < 4; mt++) {
        #pragma unroll
        for (int nt = 0; nt < 4; nt++) {
            int row = bm + wm * 64 + mt * 16 + g;
            int col = bn + wn * 32 + nt * 8 + tg * 2;
            float* c = acc[mt][nt];
            *(float2*)(C + (size_t)row * N + col)       = make_float2(c[0], c[1]);
            *(float2*)(C + (size_t)(row + 8) * N + col) = make_float2(c[2], c[3]);
        }
    }
}

// ---------------------------------------------------------------------------
// Flash attention (round-14 form, unchanged): mma.sync bf16 split, 128-key
// tiles, 2-stage 64KB ring, 1 CTA/SM, fused split epilogue.
// ---------------------------------------------------------------------------
#define KV2_BYTES 65536
#define ASMEM (32768 + 2 * KV2_BYTES)   // 163840

__global__ __launch_bounds__(256, 1) void attn_mma(
    const __nv_bfloat16* __restrict__ Qph, const __nv_bfloat16* __restrict__ Qpl,
    const __nv_bfloat16* __restrict__ Kvp, __nv_bfloat16* __restrict__ Ahl)
{
    extern __shared__ __align__(1024) char asmem[];
    __shared__ __align__(8) uint64_t mbar_s[3];
    const uint32_t base = smem_u32(asmem);

    const int h   = blockIdx.y;
    const int bx  = (gridDim.x - 1) - blockIdx.x;   // heavy blocks first
    const int q0  = bx * 128;
    const int tid = threadIdx.x;
    const int w   = tid >> 5;
    const int lane = tid & 31;
    const int g   = lane >> 2;
    const int cq  = lane & 3;
    const int lrow = (lane & 7) + ((lane >> 3) & 1) * 8;
    const int lkof = (lane >> 4) * 8;
    const int ntiles = (q0 + 128) >> 7;             // 128-key tiles

    if (tid == 0) {
        #pragma unroll
        for (int j = 0; j < 3; j++) MBARRIER_INIT(smem_u32(&mbar_s[j]), 1);
    }
    __syncthreads();
    uint32_t mb0 = smem_u32(&mbar_s[0]);
    uint32_t mb1 = smem_u32(&mbar_s[1]);
    uint32_t mbq = smem_u32(&mbar_s[2]);

    auto issue_kv = [&](int s, int tt) {
        uint32_t m = (s == 0) ? mb0 : mb1;
        MBARRIER_EXPECT_TX(m, KV2_BYTES);
        bulk_g2s(base + 32768 + s * KV2_BYTES,
                 (const char*)Kvp + (size_t)(h * (TT / 64) + 2 * tt) * 32768,
                 KV2_BYTES, m);
    };

    if (tid == 0) {
        MBARRIER_EXPECT_TX(mbq, 32768);
        bulk_g2s(base,         (const char*)Qph + ((size_t)h * TT + q0) * 128, 16384, mbq);
        bulk_g2s(base + 16384, (const char*)Qpl + ((size_t)h * TT + q0) * 128, 16384, mbq);
        issue_kv(0, 0);
        if (1 < ntiles) issue_kv(1, 1);
    }

    MBARRIER_WAIT_PARITY(mbq, 0);
    uint32_t qh[4][4], ql[4][4];
    #pragma unroll
    for (int ks = 0; ks < 4; ks++) {
        uint32_t ro = (uint32_t)(w * 16 + lrow) * 128;
        uint32_t kb = (uint32_t)(ks * 16 + lkof) * 2;
        ldsm_x4(qh[ks][0], qh[ks][1], qh[ks][2], qh[ks][3], base + swz(ro + kb));
        ldsm_x4(ql[ks][0], ql[ks][1], ql[ks][2], ql[ks][3], base + 16384 + swz(ro + kb));
    }

    float o[8][4];
    #pragma unroll
    for (int dt = 0; dt < 8; dt++)
        #pragma unroll
        for (int c = 0; c < 4; c++) o[dt][c] = 0.f;
    float m0 = -INFINITY, m1 = -INFINITY, lp0 = 0.f, lp1 = 0.f;

    const int row0 = q0 + w * 16 + g;
    int ph0 = 0, ph1 = 0;
    int s = 0;

    for (int t = 0; t < ntiles; t++) {
        const int k0 = t << 7;
        if (s == 0) { MBARRIER_WAIT_PARITY(mb0, ph0); ph0 ^= 1; }
        else        { MBARRIER_WAIT_PARITY(mb1, ph1); ph1 ^= 1; }

        uint32_t sb = base + 32768 + s * KV2_BYTES;

        float sc_[16][4];
        #pragma unroll
        for (int nt = 0; nt < 16; nt++)
            #pragma unroll
            for (int c = 0; c < 4; c++) sc_[nt][c] = 0.f;

        #pragma unroll
        for (int ks = 0; ks < 4; ks++) {
            const uint32_t kb = (uint32_t)(ks * 16 + lkof) * 2;
            #pragma unroll
            for (int p = 0; p < 8; p++) {
                uint32_t blk = (uint32_t)(p >> 2) * 32768;
                uint32_t ro = (uint32_t)((p & 3) * 16 + lrow) * 128;
                uint32_t r0, r1, r2, r3, u0, u1, u2, u3;
                ldsm_x4(r0, r1, r2, r3, sb + blk + swz(ro + kb));
                ldsm_x4(u0, u1, u2, u3, sb + blk + 8192 + swz(ro + kb));
                float* s0 = sc_[2 * p];
                float* s1 = sc_[2 * p + 1];
                mma16816(s0[0], s0[1], s0[2], s0[3], qh[ks][0], qh[ks][1], qh[ks][2], qh[ks][3], r0, r2);
                mma16816(s0[0], s0[1], s0[2], s0[3], qh[ks][0], qh[ks][1], qh[ks][2], qh[ks][3], u0, u2);
                mma16816(s0[0], s0[1], s0[2], s0[3], ql[ks][0], ql[ks][1], ql[ks][2], ql[ks][3], r0, r2);
                mma16816(s1[0], s1[1], s1[2], s1[3], qh[ks][0], qh[ks][1], qh[ks][2], qh[ks][3], r1, r3);
                mma16816(s1[0], s1[1], s1[2], s1[3], qh[ks][0], qh[ks][1], qh[ks][2], qh[ks][3], u1, u3);
                mma16816(s1[0], s1[1], s1[2], s1[3], ql[ks][0], ql[ks][1], ql[ks][2], ql[ks][3], r1, r3);
            }
        }

        if (k0 + 128 > q0) {
            #pragma unroll
            for (int nt = 0; nt < 16; nt++) {
                int col = k0 + nt * 8 + 2 * cq;
                if (col     > row0)     sc_[nt][0] = -INFINITY;
                if (col + 1 > row0)     sc_[nt][1] = -INFINITY;
                if (col     > row0 + 8) sc_[nt][2] = -INFINITY;
                if (col + 1 > row0 + 8) sc_[nt][3] = -INFINITY;
            }
        }

        float mx0 = -INFINITY, mx1 = -INFINITY;
        #pragma unroll
        for (int nt = 0; nt < 16; nt++) {
            mx0 = fmaxf(mx0, fmaxf(sc_[nt][0], sc_[nt][1]));
            mx1 = fmaxf(mx1, fmaxf(sc_[nt][2], sc_[nt][3]));
        }
        mx0 = fmaxf(mx0, __shfl_xor_sync(0xffffffffu, mx0, 1));
        mx0 = fmaxf(mx0, __shfl_xor_sync(0xffffffffu, mx0, 2));
        mx1 = fmaxf(mx1, __shfl_xor_sync(0xffffffffu, mx1, 1));
        mx1 = fmaxf(mx1, __shfl_xor_sync(0xffffffffu, mx1, 2));
        float mn0 = fmaxf(m0, mx0), mn1 = fmaxf(m1, mx1);
        float cf0 = fast_exp2(m0 - mn0), cf1 = fast_exp2(m1 - mn1);
        m0 = mn0; m1 = mn1;
        lp0 *= cf0; lp1 *= cf1;
        #pragma unroll
        for (int dt = 0; dt < 8; dt++) {
            o[dt][0] *= cf0; o[dt][1] *= cf0;
            o[dt][2] *= cf1; o[dt][3] *= cf1;
        }

        #pragma unroll
        for (int kk = 0; kk < 8; kk++) {
            float p0 = fast_exp2(sc_[2 * kk][0] - m0);
            float p1 = fast_exp2(sc_[2 * kk][1] - m0);
            float p2 = fast_exp2(sc_[2 * kk][2] - m1);
            float p3 = fast_exp2(sc_[2 * kk][3] - m1);
            float p4 = fast_exp2(sc_[2 * kk + 1][0] - m0);
            float p5 = fast_exp2(sc_[2 * kk + 1][1] - m0);
            float p6 = fast_exp2(sc_[2 * kk + 1][2] - m1);
            float p7 = fast_exp2(sc_[2 * kk + 1][3] - m1);
            lp0 += p0 + p1 + p4 + p5;
            lp1 += p2 + p3 + p6 + p7;
            float h0 = __bfloat162float(__float2bfloat16(p0));
            float h1 = __bfloat162float(__float2bfloat16(p1));
            float h2 = __bfloat162float(__float2bfloat16(p2));
            float h3 = __bfloat162float(__float2bfloat16(p3));
            float h4 = __bfloat162float(__float2bfloat16(p4));
            float h5 = __bfloat162float(__float2bfloat16(p5));
            float h6 = __bfloat162float(__float2bfloat16(p6));
            float h7 = __bfloat162float(__float2bfloat16(p7));
            uint32_t ah0 = pack_bf16x2(h0, h1);
            uint32_t ah1 = pack_bf16x2(h2, h3);
            uint32_t ah2 = pack_bf16x2(h4, h5);
            uint32_t ah3 = pack_bf16x2(h6, h7);
            uint32_t al0 = pack_bf16x2(p0 - h0, p1 - h1);
            uint32_t al1 = pack_bf16x2(p2 - h2, p3 - h3);
            uint32_t al2 = pack_bf16x2(p4 - h4, p5 - h5);
            uint32_t al3 = pack_bf16x2(p6 - h6, p7 - h7);

            uint32_t vblk = (uint32_t)(kk >> 2) * 32768;
            const uint32_t kb = (uint32_t)((kk & 3) * 16 + lkof) * 2;
            #pragma unroll
            for (int dp = 0; dp < 4; dp++) {
                uint32_t ro = (uint32_t)(dp * 16 + lrow) * 128;
                uint32_t v0, v1, v2, v3, x0, x1, x2, x3;
                ldsm_x4(v0, v1, v2, v3, sb + vblk + 16384 + swz(ro + kb));
                ldsm_x4(x0, x1, x2, x3, sb + vblk + 24576 + swz(ro + kb));
                float* oa = o[2 * dp];
                float* ob = o[2 * dp + 1];
                mma16816(oa[0], oa[1], oa[2], oa[3], ah0, ah1, ah2, ah3, v0, v2);
                mma16816(oa[0], oa[1], oa[2], oa[3], ah0, ah1, ah2, ah3, x0, x2);
                mma16816(oa[0], oa[1], oa[2], oa[3], al0, al1, al2, al3, v0, v2);
                mma16816(ob[0], ob[1], ob[2], ob[3], ah0, ah1, ah2, ah3, v1, v3);
                mma16816(ob[0], ob[1], ob[2], ob[3], ah0, ah1, ah2, ah3, x1, x3);
                mma16816(ob[0], ob[1], ob[2], ob[3], al0, al1, al2, al3, v1, v3);
            }
        }
        __syncthreads();
        if (tid == 0 && t + 2 < ntiles) issue_kv(s, t + 2);
        s ^= 1;
    }

    lp0 += __shfl_xor_sync(0xffffffffu, lp0, 1);
    lp0 += __shfl_xor_sync(0xffffffffu, lp0, 2);
    lp1 += __shfl_xor_sync(0xffffffffu, lp1, 1);
    lp1 += __shfl_xor_sync(0xffffffffu, lp1, 2);
    float inv0 = 1.0f / lp0, inv1 = 1.0f / lp1;
    #pragma unroll
    for (int dt = 0; dt < 8; dt++) {
        int col = h * HDIM + dt * 8 + 2 * cq;
        int kc = col >> 5, cin = col & 31;
        float a0 = o[dt][0] * inv0, a1 = o[dt][1] * inv0;
        float b0 = o[dt][2] * inv1, b1 = o[dt][3] * inv1;
        float a0h = __bfloat162float(__float2bfloat16(a0));
        float a1h = __bfloat162float(__float2bfloat16(a1));
        float b0h = __bfloat162float(__float2bfloat16(b0));
        float b1h = __bfloat162float(__float2bfloat16(b1));
        size_t r0b = ((size_t)kc * TT + row0) * 128;
        size_t r1b = ((size_t)kc * TT + row0 + 8) * 128;
        *(uint32_t*)((char*)Ahl + swzs(r0b + (size_t)cin * 2))      = pack_bf16x2(a0h, a1h);
        *(uint32_t*)((char*)Ahl + swzs(r0b + 64 + (size_t)cin * 2)) = pack_bf16x2(a0 - a0h, a1 - a1h);
        *(uint32_t*)((char*)Ahl + swzs(r1b + (size_t)cin * 2))      = pack_bf16x2(b0h, b1h);
        *(uint32_t*)((char*)Ahl + swzs(r1b + 64 + (size_t)cin * 2)) = pack_bf16x2(b0 - b0h, b1 - b1h);
    }
}

// ---------------------------------------------------------------------------
extern "C" void kernel_launch(void* const* d_in, const int* in_sizes, int n_in,
                              void* d_out, int out_size)
{
    const float* x    = (const float*)d_in[0];
    const float* wqkv = (const float*)d_in[1];
    const float* wout = (const float*)d_in[2];
    float* out = (float*)d_out;

    float* qkv;
    __nv_bfloat16 *xhl, *w1hl, *w2hl, *ahl, *qph, *qpl, *kvp;
    cudaGetSymbolAddress((void**)&qkv,  g_qkv);
    cudaGetSymbolAddress((void**)&xhl,  g_xhl);
    cudaGetSymbolAddress((void**)&w1hl, g_w1hl);
    cudaGetSymbolAddress((void**)&w2hl, g_w2hl);
    cudaGetSymbolAddress((void**)&ahl,  g_ahl);
    cudaGetSymbolAddress((void**)&qph,  g_qph);
    cudaGetSymbolAddress((void**)&qpl,  g_qpl);
    cudaGetSymbolAddress((void**)&kvp,  g_kvp);

    cudaFuncSetAttribute(tc_gemm,  cudaFuncAttributeMaxDynamicSharedMemorySize, GSMEM);
    cudaFuncSetAttribute(attn_mma, cudaFuncAttributeMaxDynamicSharedMemorySize, ASMEM);

    // prep
    split_chunk<<<(TT * DD / 8 + 255) / 256, 256>>>(x, xhl, TT, DD);
    wsplit_chunk<<<dim3(3 * DD / 32, DD / 32), dim3(32, 8)>>>(wqkv, w1hl, DD, 3 * DD);
    wsplit_chunk<<<dim3(DD / 32, DD / 32), dim3(32, 8)>>>(wout, w2hl, DD, DD);

    // 1) QKV projection (warp-grained stage release)
    tc_gemm<<<dim3(3 * DD / 128, TT / 128), 256, GSMEM>>>(xhl, w1hl, qkv, TT, 3 * DD, DD);

    // attention operand packing
    kv_pack<<<dim3(TT / 64, NH), 256>>>(qkv, qph, qpl, kvp);

    // 2) causal attention (128-key tiles, 2-stage 64KB ring)
    attn_mma<<<dim3(TT / 128, NH), 256, ASMEM>>>(qph, qpl, kvp, ahl);

    // 3) output projection
    tc_gemm<<<dim3(DD / 128, TT / 128), 256, GSMEM>>>(ahl, w2hl, out, TT, DD, DD);
}

// round 16
// speedup vs baseline: 1.0640x; 1.0640x over previous
#include <cuda_runtime.h>
#include <cuda_bf16.h>
#include <math.h>
#include <stdint.h>

#define TT 4096
#define DD 1024
#define NH 16
#define HDIM 64

// ---------------------------------------------------------------------------
// Scratch (allocation-free rule: device globals). 16B-aligned.
// GEMM operands chunk-major hi/lo interleaved, SW128-preswizzled:
//   [kc][row][32 hi bf16 | 32 lo bf16] (128B rows, kc = K/32)
// Attention: Q preswizzled rows [h][t][64] hi/lo; K/V packed per
// (head, 64-key tile) as one 32KB block: Kh|Kl|Vth|Vtl (8KB each).
// Two consecutive blocks form one 64KB 128-key stage.
// ---------------------------------------------------------------------------
__device__ __align__(16) __nv_bfloat16 g_xhl[(size_t)TT * DD * 2];
__device__ __align__(16) __nv_bfloat16 g_w1hl[(size_t)3 * DD * DD * 2];
__device__ __align__(16) __nv_bfloat16 g_w2hl[(size_t)DD * DD * 2];
__device__ __align__(16) __nv_bfloat16 g_ahl[(size_t)TT * DD * 2];
__device__ __align__(16) __nv_bfloat16 g_qph[(size_t)NH * TT * HDIM];
__device__ __align__(16) __nv_bfloat16 g_qpl[(size_t)NH * TT * HDIM];
__device__ __align__(16) __nv_bfloat16 g_kvp[(size_t)NH * (TT / 64) * 16384]; // 32MB

// ---------------------------------------------------------------------------
// PTX helpers
// ---------------------------------------------------------------------------
__device__ __forceinline__ uint32_t smem_u32(const void* p) {
    uint32_t a;
    asm("{ .reg .u64 t; cvta.to.shared.u64 t, %1; cvt.u32.u64 %0, t; }" : "=r"(a) : "l"(p));
    return a;
}
__device__ __forceinline__ void ldsm_x4(uint32_t& r0, uint32_t& r1, uint32_t& r2, uint32_t& r3,
                                        uint32_t addr) {
    asm volatile("ldmatrix.sync.aligned.m8n8.x4.shared.b16 {%0,%1,%2,%3}, [%4];"
                 : "=r"(r0), "=r"(r1), "=r"(r2), "=r"(r3) : "r"(addr));
}
__device__ __forceinline__ void mma16816(float& c0, float& c1, float& c2, float& c3,
                                         uint32_t a0, uint32_t a1, uint32_t a2, uint32_t a3,
                                         uint32_t b0, uint32_t b1) {
    asm("mma.sync.aligned.m16n8k16.row.col.f32.bf16.bf16.f32 "
        "{%0,%1,%2,%3}, {%4,%5,%6,%7}, {%8,%9}, {%0,%1,%2,%3};"
        : "+f"(c0), "+f"(c1), "+f"(c2), "+f"(c3)
        : "r"(a0), "r"(a1), "r"(a2), "r"(a3), "r"(b0), "r"(b1));
}
__device__ __forceinline__ void bulk_g2s(uint32_t dst, const void* src, uint32_t bytes,
                                         uint32_t mbar) {
    asm volatile("cp.async.bulk.shared::cluster.global.mbarrier::complete_tx::bytes "
                 "[%0], [%1], %2, [%3];"
                 :: "r"(dst), "l"(src), "r"(bytes), "r"(mbar) : "memory");
}
#define MBARRIER_INIT(mb, c) \
    asm volatile("mbarrier.init.shared.b64 [%0], %1;" :: "r"((uint32_t)(mb)), "r"((uint32_t)(c)) : "memory")
#define MBARRIER_EXPECT_TX(mb, bytes) \
    asm volatile("mbarrier.arrive.expect_tx.shared.b64 _, [%0], %1;" \
                 :: "r"((uint32_t)(mb)), "r"((uint32_t)(bytes)) : "memory")
#define MBARRIER_WAIT_PARITY(mb, ph) do { \
    uint32_t _m = (uint32_t)(mb), _p = (uint32_t)(ph), _d; \
    asm volatile("{ .reg .pred p; mbarrier.try_wait.parity.acquire.cta.shared::cta.b64 p, [%1], %2; " \
                 "selp.b32 %0, 1, 0, p; }" : "=r"(_d) : "r"(_m), "r"(_p) : "memory"); \
    if (!_d) { \
        asm volatile("{ .reg .pred P1; WL_%=: mbarrier.try_wait.parity.acquire.cta.shared::cta.b64 P1, [%0], %1, 0x989680; " \
                     "@P1 bra.uni WD_%=; bra.uni WL_%=; WD_%=: }" :: "r"(_m), "r"(_p) : "memory"); \
    } \
} while (0)

__device__ __forceinline__ float fast_exp2(float x) {
    float y;
    asm("ex2.approx.ftz.f32 %0, %1;" : "=f"(y) : "f"(x));
    return y;
}
__device__ __forceinline__ uint32_t pack_bf16x2(float a, float b) {
    __nv_bfloat162 t = __floats2bfloat162_rn(a, b);
    return *reinterpret_cast<uint32_t*>(&t);
}
__device__ __forceinline__ uint32_t swz(uint32_t o)  { return o ^ ((o >> 3) & 0x70); }
__device__ __forceinline__ size_t   swzs(size_t o)   { return o ^ ((o >> 3) & 0x70); }

__device__ __forceinline__ void split16(const float (&f)[16],
                                        uint4& h0, uint4& h1, uint4& l0, uint4& l1)
{
    float hh[16];
    #pragma unroll
    for (int i = 0; i < 16; i++) hh[i] = __bfloat162float(__float2bfloat16(f[i]));
    h0 = make_uint4(pack_bf16x2(hh[0], hh[1]),  pack_bf16x2(hh[2], hh[3]),
                    pack_bf16x2(hh[4], hh[5]),  pack_bf16x2(hh[6], hh[7]));
    h1 = make_uint4(pack_bf16x2(hh[8], hh[9]),  pack_bf16x2(hh[10], hh[11]),
                    pack_bf16x2(hh[12], hh[13]), pack_bf16x2(hh[14], hh[15]));
    l0 = make_uint4(pack_bf16x2(f[0]-hh[0], f[1]-hh[1]),   pack_bf16x2(f[2]-hh[2], f[3]-hh[3]),
                    pack_bf16x2(f[4]-hh[4], f[5]-hh[5]),   pack_bf16x2(f[6]-hh[6], f[7]-hh[7]));
    l1 = make_uint4(pack_bf16x2(f[8]-hh[8], f[9]-hh[9]),   pack_bf16x2(f[10]-hh[10], f[11]-hh[11]),
                    pack_bf16x2(f[12]-hh[12], f[13]-hh[13]), pack_bf16x2(f[14]-hh[14], f[15]-hh[15]));
}

// ---------------------------------------------------------------------------
// fp32 [M][K] -> chunk-major hi/lo preswizzled
// ---------------------------------------------------------------------------
__global__ void split_chunk(const float* __restrict__ s, __nv_bfloat16* __restrict__ o,
                            int M, int K)
{
    size_t i8 = ((size_t)blockIdx.x * blockDim.x + threadIdx.x) * 8;
    if (i8 >= (size_t)M * K) return;
    int m  = (int)(i8 / K);
    int k  = (int)(i8 % K);
    int kc = k >> 5, kin = k & 31;
    float4 v0 = *(const float4*)(s + i8);
    float4 v1 = *(const float4*)(s + i8 + 4);
    float f[8] = {v0.x, v0.y, v0.z, v0.w, v1.x, v1.y, v1.z, v1.w};
    float h[8];
    #pragma unroll
    for (int j = 0; j < 8; j++) h[j] = __bfloat162float(__float2bfloat16(f[j]));
    uint4 hu, lu;
    hu.x = pack_bf16x2(h[0], h[1]); hu.y = pack_bf16x2(h[2], h[3]);
    hu.z = pack_bf16x2(h[4], h[5]); hu.w = pack_bf16x2(h[6], h[7]);
    lu.x = pack_bf16x2(f[0]-h[0], f[1]-h[1]); lu.y = pack_bf16x2(f[2]-h[2], f[3]-h[3]);
    lu.z = pack_bf16x2(f[4]-h[4], f[5]-h[5]); lu.w = pack_bf16x2(f[6]-h[6], f[7]-h[7]);
    size_t rowb = ((size_t)kc * M + m) * 128;
    *(uint4*)((char*)o + swzs(rowb + (size_t)kin * 2))      = hu;
    *(uint4*)((char*)o + swzs(rowb + 64 + (size_t)kin * 2)) = lu;
}

// ---------------------------------------------------------------------------
// w[K][N] fp32 -> wT chunk-major hi/lo preswizzled
// ---------------------------------------------------------------------------
__global__ void wsplit_chunk(const float* __restrict__ w, __nv_bfloat16* __restrict__ o,
                             int K, int N)
{
    __shared__ float t[32][33];
    int n0 = blockIdx.x * 32, k0 = blockIdx.y * 32;
    int tx = threadIdx.x, ty = threadIdx.y;
    for (int j = ty; j < 32; j += 8)
        t[j][tx] = w[(size_t)(k0 + j) * N + n0 + tx];
    __syncthreads();
    float f0 = t[ty * 4 + 0][tx], f1 = t[ty * 4 + 1][tx];
    float f2 = t[ty * 4 + 2][tx], f3 = t[ty * 4 + 3][tx];
    float h0 = __bfloat162float(__float2bfloat16(f0));
    float h1 = __bfloat162float(__float2bfloat16(f1));
    float h2 = __bfloat162float(__float2bfloat16(f2));
    float h3 = __bfloat162float(__float2bfloat16(f3));
    uint2 hu, lu;
    hu.x = pack_bf16x2(h0, h1); hu.y = pack_bf16x2(h2, h3);
    lu.x = pack_bf16x2(f0 - h0, f1 - h1); lu.y = pack_bf16x2(f2 - h2, f3 - h3);
    size_t rowb = ((size_t)blockIdx.y * N + n0 + tx) * 128;
    *(uint2*)((char*)o + swzs(rowb + (size_t)ty * 8))      = hu;
    *(uint2*)((char*)o + swzs(rowb + 64 + (size_t)ty * 8)) = lu;
}

// ---------------------------------------------------------------------------
// mma.sync bf16 split GEMM (round-14 measured-best form, EXACT revert):
// 2-stage bulk pipeline, per-chunk __syncthreads. fp32 output.
// ---------------------------------------------------------------------------
#define CH_BYTES 16384
#define STG_BYTES (2 * CH_BYTES)
#define GSMEM (2 * STG_BYTES)        // 65536

__global__ __launch_bounds__(256, 2) void tc_gemm(
    const __nv_bfloat16* __restrict__ Ahl, const __nv_bfloat16* __restrict__ Bhl,
    float* __restrict__ C, int M, int N, int K)
{
    extern __shared__ __align__(1024) char dsm[];
    __shared__ __align__(8) uint64_t mbar_s[2];
    const uint32_t base = smem_u32(dsm);

    const int tid  = threadIdx.x;
    const int wid  = tid >> 5;
    const int lane = tid & 31;
    const int wm   = wid >> 2;
    const int wn   = wid & 3;
    const int bm   = blockIdx.y * 128, bn = blockIdx.x * 128;
    const int lrow = (lane & 7) + ((lane >> 3) & 1) * 8;
    const int lkof = (lane >> 4) * 8;

    if (tid == 0) {
        MBARRIER_INIT(smem_u32(&mbar_s[0]), 1);
        MBARRIER_INIT(smem_u32(&mbar_s[1]), 1);
    }
    __syncthreads();
    uint32_t mb0 = smem_u32(&mbar_s[0]);
    uint32_t mb1 = smem_u32(&mbar_s[1]);

    const int NCH = K / 32;

    auto issue = [&](int s, int t) {
        uint32_t m = s ? mb1 : mb0;
        MBARRIER_EXPECT_TX(m, STG_BYTES);
        const char* srcA = (const char*)Ahl + ((size_t)t * M + bm) * 128;
        const char* srcB = (const char*)Bhl + ((size_t)t * N + bn) * 128;
        uint32_t d = base + s * STG_BYTES;
        bulk_g2s(d,            srcA, CH_BYTES, m);
        bulk_g2s(d + CH_BYTES, srcB, CH_BYTES, m);
    };
    if (tid == 0) {
        issue(0, 0);
        if (NCH > 1) issue(1, 1);
    }

    float acc[4][4][4];
    #pragma unroll
    for (int mt = 0; mt < 4; mt++)
        #pragma unroll
        for (int nt = 0; nt < 4; nt++)
            #pragma unroll
            for (int c = 0; c < 4; c++) acc[mt][nt][c] = 0.f;

    int ph0 = 0, ph1 = 0;

    for (int t = 0; t < NCH; t++) {
        int s = t & 1;
        if (s == 0) { MBARRIER_WAIT_PARITY(mb0, ph0); ph0 ^= 1; }
        else        { MBARRIER_WAIT_PARITY(mb1, ph1); ph1 ^= 1; }

        uint32_t aB = base + s * STG_BYTES;
        uint32_t bB = aB + CH_BYTES;

        #pragma unroll
        for (int ks = 0; ks < 2; ks++) {
            const uint32_t kb = (uint32_t)(ks * 16 + lkof) * 2;

            uint32_t bh[4][2], bl[4][2];
            #pragma unroll
            for (int p = 0; p < 2; p++) {
                uint32_t ro = (uint32_t)(wn * 32 + p * 16 + lrow) * 128;
                uint32_t r0, r1, r2, r3;
                ldsm_x4(r0, r1, r2, r3, bB + swz(ro + kb));
                bh[p * 2][0] = r0; bh[p * 2][1] = r2;
                bh[p * 2 + 1][0] = r1; bh[p * 2 + 1][1] = r3;
                ldsm_x4(r0, r1, r2, r3, bB + swz(ro + 64 + kb));
                bl[p * 2][0] = r0; bl[p * 2][1] = r2;
                bl[p * 2 + 1][0] = r1; bl[p * 2 + 1][1] = r3;
            }

            #pragma unroll
            for (int mt = 0; mt < 4; mt++) {
                uint32_t ro = (uint32_t)(wm * 64 + mt * 16 + lrow) * 128;
                uint32_t ah0, ah1, ah2, ah3, al0, al1, al2, al3;
                ldsm_x4(ah0, ah1, ah2, ah3, aB + swz(ro + kb));
                ldsm_x4(al0, al1, al2, al3, aB + swz(ro + 64 + kb));
                #pragma unroll
                for (int nt = 0; nt < 4; nt++) {
                    float* c = acc[mt][nt];
                    mma16816(c[0], c[1], c[2], c[3], ah0, ah1, ah2, ah3,
                             bh[nt][0], bh[nt][1]);
                    mma16816(c[0], c[1], c[2], c[3], ah0, ah1, ah2, ah3,
                             bl[nt][0], bl[nt][1]);
                    mma16816(c[0], c[1], c[2], c[3], al0, al1, al2, al3,
                             bh[nt][0], bh[nt][1]);
                }
            }
        }
        __syncthreads();
        if (tid == 0 && t + 2 < NCH) issue(s, t + 2);
    }

    const int g  = lane >> 2;
    const int tg = lane & 3;
    #pragma unroll
    for (int mt = 0; mt < 4; mt++) {
        #pragma unroll
        for (int nt = 0; nt < 4; nt++) {
            int row = bm + wm * 64 + mt * 16 + g;
            int col = bn + wn * 32 + nt * 8 + tg * 2;
            float* c = acc[mt][nt];
            *(float2*)(C + (size_t)row * N + col)       = make_float2(c[0], c[1]);
            *(float2*)(C + (size_t)(row + 8) * N + col) = make_float2(c[2], c[3]);
        }
    }
}

// ---------------------------------------------------------------------------
// tc_gemm_qkv: identical mainloop; epilogue writes attention operands
// DIRECTLY (replaces kv_pack + the 48MB fp32 qkv round trip).
// Tiles never straddle Q/K/V boundaries (1024 % 128 == 0).
//   region 0 (cols [0,1024)):    Q -> qph/qpl rows, scaled by sc
//   region 1 (cols [1024,2048)): K -> kvp K-blocks
//   region 2 (cols [2048,3072)): V -> smem transpose -> kvp V-blocks
// ---------------------------------------------------------------------------
#define VPITCH 132
#define GSMEM_QKV (VPITCH * 128 * 4)   // 67584 > 2*STG_BYTES

__global__ __launch_bounds__(256, 2) void tc_gemm_qkv(
    const __nv_bfloat16* __restrict__ Ahl, const __nv_bfloat16* __restrict__ Bhl,
    __nv_bfloat16* __restrict__ Qph, __nv_bfloat16* __restrict__ Qpl,
    __nv_bfloat16* __restrict__ Kvp, int M, int N, int K)
{
    extern __shared__ __align__(1024) char dsm[];
    __shared__ __align__(8) uint64_t mbar_s[2];
    const uint32_t base = smem_u32(dsm);

    const int tid  = threadIdx.x;
    const int wid  = tid >> 5;
    const int lane = tid & 31;
    const int wm   = wid >> 2;
    const int wn   = wid & 3;
    const int bm   = blockIdx.y * 128, bn = blockIdx.x * 128;
    const int lrow = (lane & 7) + ((lane >> 3) & 1) * 8;
    const int lkof = (lane >> 4) * 8;

    if (tid == 0) {
        MBARRIER_INIT(smem_u32(&mbar_s[0]), 1);
        MBARRIER_INIT(smem_u32(&mbar_s[1]), 1);
    }
    __syncthreads();
    uint32_t mb0 = smem_u32(&mbar_s[0]);
    uint32_t mb1 = smem_u32(&mbar_s[1]);

    const int NCH = K / 32;

    auto issue = [&](int s, int t) {
        uint32_t m = s ? mb1 : mb0;
        MBARRIER_EXPECT_TX(m, STG_BYTES);
        const char* srcA = (const char*)Ahl + ((size_t)t * M + bm) * 128;
        const char* srcB = (const char*)Bhl + ((size_t)t * N + bn) * 128;
        uint32_t d = base + s * STG_BYTES;
        bulk_g2s(d,            srcA, CH_BYTES, m);
        bulk_g2s(d + CH_BYTES, srcB, CH_BYTES, m);
    };
    if (tid == 0) {
        issue(0, 0);
        if (NCH > 1) issue(1, 1);
    }

    float acc[4][4][4];
    #pragma unroll
    for (int mt = 0; mt < 4; mt++)
        #pragma unroll
        for (int nt = 0; nt < 4; nt++)
            #pragma unroll
            for (int c = 0; c < 4; c++) acc[mt][nt][c] = 0.f;

    int ph0 = 0, ph1 = 0;

    for (int t = 0; t < NCH; t++) {
        int s = t & 1;
        if (s == 0) { MBARRIER_WAIT_PARITY(mb0, ph0); ph0 ^= 1; }
        else        { MBARRIER_WAIT_PARITY(mb1, ph1); ph1 ^= 1; }

        uint32_t aB = base + s * STG_BYTES;
        uint32_t bB = aB + CH_BYTES;

        #pragma unroll
        for (int ks = 0; ks < 2; ks++) {
            const uint32_t kb = (uint32_t)(ks * 16 + lkof) * 2;

            uint32_t bh[4][2], bl[4][2];
            #pragma unroll
            for (int p = 0; p < 2; p++) {
                uint32_t ro = (uint32_t)(wn * 32 + p * 16 + lrow) * 128;
                uint32_t r0, r1, r2, r3;
                ldsm_x4(r0, r1, r2, r3, bB + swz(ro + kb));
                bh[p * 2][0] = r0; bh[p * 2][1] = r2;
                bh[p * 2 + 1][0] = r1; bh[p * 2 + 1][1] = r3;
                ldsm_x4(r0, r1, r2, r3, bB + swz(ro + 64 + kb));
                bl[p * 2][0] = r0; bl[p * 2][1] = r2;
                bl[p * 2 + 1][0] = r1; bl[p * 2 + 1][1] = r3;
            }

            #pragma unroll
            for (int mt = 0; mt < 4; mt++) {
                uint32_t ro = (uint32_t)(wm * 64 + mt * 16 + lrow) * 128;
                uint32_t ah0, ah1, ah2, ah3, al0, al1, al2, al3;
                ldsm_x4(ah0, ah1, ah2, ah3, aB + swz(ro + kb));
                ldsm_x4(al0, al1, al2, al3, aB + swz(ro + 64 + kb));
                #pragma unroll
                for (int nt = 0; nt < 4; nt++) {
                    float* c = acc[mt][nt];
                    mma16816(c[0], c[1], c[2], c[3], ah0, ah1, ah2, ah3,
                             bh[nt][0], bh[nt][1]);
                    mma16816(c[0], c[1], c[2], c[3], ah0, ah1, ah2, ah3,
                             bl[nt][0], bl[nt][1]);
                    mma16816(c[0], c[1], c[2], c[3], al0, al1, al2, al3,
                             bh[nt][0], bh[nt][1]);
                }
            }
        }
        __syncthreads();
        if (tid == 0 && t + 2 < NCH) issue(s, t + 2);
    }
    // after the final per-chunk __syncthreads, stage smem is reusable

    const int g  = lane >> 2;
    const int tg = lane & 3;
    const int region = bn >> 10;          // 0=Q, 1=K, 2=V
    const int cb = bn & 1023;             // within-region column base
    const float sc = 0.125f * 1.4426950408889634f;

    if (region == 0) {
        // Q: scale + split, preswizzled rows [h][t][64]
        #pragma unroll
        for (int mt = 0; mt < 4; mt++) {
            #pragma unroll
            for (int nt = 0; nt < 4; nt++) {
                int lc = cb + wn * 32 + nt * 8 + tg * 2;
                int hh = lc >> 6, d = lc & 63;
                float* c = acc[mt][nt];
                #pragma unroll
                for (int half = 0; half < 2; half++) {
                    int trow = bm + wm * 64 + mt * 16 + g + half * 8;
                    float a0 = c[2 * half] * sc, a1 = c[2 * half + 1] * sc;
                    float h0 = __bfloat162float(__float2bfloat16(a0));
                    float h1 = __bfloat162float(__float2bfloat16(a1));
                    size_t rb = ((size_t)hh * TT + trow) * 128 + (size_t)d * 2;
                    *(uint32_t*)((char*)Qph + swzs(rb)) = pack_bf16x2(h0, h1);
                    *(uint32_t*)((char*)Qpl + swzs(rb)) = pack_bf16x2(a0 - h0, a1 - h1);
                }
            }
        }
    } else if (region == 1) {
        // K: split into kvp K-blocks
        #pragma unroll
        for (int mt = 0; mt < 4; mt++) {
            #pragma unroll
            for (int nt = 0; nt < 4; nt++) {
                int lc = cb + wn * 32 + nt * 8 + tg * 2;
                int hh = lc >> 6, d = lc & 63;
                float* c = acc[mt][nt];
                #pragma unroll
                for (int half = 0; half < 2; half++) {
                    int trow = bm + wm * 64 + mt * 16 + g + half * 8;
                    float a0 = c[2 * half], a1 = c[2 * half + 1];
                    float h0 = __bfloat162float(__float2bfloat16(a0));
                    float h1 = __bfloat162float(__float2bfloat16(a1));
                    size_t kvb = (size_t)(hh * (TT / 64) + (trow >> 6)) * 32768;
                    size_t kr  = (size_t)(trow & 63) * 128 + (size_t)d * 2;
                    *(uint32_t*)((char*)Kvp + kvb + swzs(kr))        = pack_bf16x2(h0, h1);
                    *(uint32_t*)((char*)Kvp + kvb + 8192 + swzs(kr)) = pack_bf16x2(a0 - h0, a1 - h1);
                }
            }
        }
    } else {
        // V: stage fp32 tile in smem, transpose, emit kvp V-blocks (kv_pack style)
        float* vsm = (float*)dsm;
        #pragma unroll
        for (int mt = 0; mt < 4; mt++) {
            #pragma unroll
            for (int nt = 0; nt < 4; nt++) {
                int rl = wm * 64 + mt * 16 + g;
                int cl = wn * 32 + nt * 8 + tg * 2;
                float* c = acc[mt][nt];
                vsm[rl * VPITCH + cl]           = c[0];
                vsm[rl * VPITCH + cl + 1]       = c[1];
                vsm[(rl + 8) * VPITCH + cl]     = c[2];
                vsm[(rl + 8) * VPITCH + cl + 1] = c[3];
            }
        }
        __syncthreads();
        const int d  = tid >> 2;
        const int c0 = (tid & 3) * 16;
        #pragma unroll
        for (int b = 0; b < 2; b++) {
            #pragma unroll
            for (int hhp = 0; hhp < 2; hhp++) {
                int hh = (cb >> 6) + hhp;
                size_t kvb = (size_t)(hh * (TT / 64) + (bm >> 6) + b) * 32768;
                float vf[16];
                #pragma unroll
                for (int i = 0; i < 16; i++)
                    vf[i] = vsm[(64 * b + c0 + i) * VPITCH + 64 * hhp + d];
                uint4 h0, h1, l0, l1;
                split16(vf, h0, h1, l0, l1);
                size_t vr = (size_t)d * 128 + (size_t)c0 * 2;
                *(uint4*)((char*)Kvp + kvb + 16384 + swzs(vr))      = h0;
                *(uint4*)((char*)Kvp + kvb + 16384 + swzs(vr + 16)) = h1;
                *(uint4*)((char*)Kvp + kvb + 24576 + swzs(vr))      = l0;
                *(uint4*)((char*)Kvp + kvb + 24576 + swzs(vr + 16)) = l1;
            }
        }
    }
}

// ---------------------------------------------------------------------------
// Flash attention (round-14 form, unchanged): mma.sync bf16 split, 128-key
// tiles, 2-stage 64KB ring, 1 CTA/SM, fused split epilogue.
// ---------------------------------------------------------------------------
#define KV2_BYTES 65536
#define ASMEM (32768 + 2 * KV2_BYTES)   // 163840

__global__ __launch_bounds__(256, 1) void attn_mma(
    const __nv_bfloat16* __restrict__ Qph, const __nv_bfloat16* __restrict__ Qpl,
    const __nv_bfloat16* __restrict__ Kvp, __nv_bfloat16* __restrict__ Ahl)
{
    extern __shared__ __align__(1024) char asmem[];
    __shared__ __align__(8) uint64_t mbar_s[3];
    const uint32_t base = smem_u32(asmem);

    const int h   = blockIdx.y;
    const int bx  = (gridDim.x - 1) - blockIdx.x;   // heavy blocks first
    const int q0  = bx * 128;
    const int tid = threadIdx.x;
    const int w   = tid >> 5;
    const int lane = tid & 31;
    const int g   = lane >> 2;
    const int cq  = lane & 3;
    const int lrow = (lane & 7) + ((lane >> 3) & 1) * 8;
    const int lkof = (lane >> 4) * 8;
    const int ntiles = (q0 + 128) >> 7;

    if (tid == 0) {
        #pragma unroll
        for (int j = 0; j < 3; j++) MBARRIER_INIT(smem_u32(&mbar_s[j]), 1);
    }
    __syncthreads();
    uint32_t mb0 = smem_u32(&mbar_s[0]);
    uint32_t mb1 = smem_u32(&mbar_s[1]);
    uint32_t mbq = smem_u32(&mbar_s[2]);

    auto issue_kv = [&](int s, int tt) {
        uint32_t m = (s == 0) ? mb0 : mb1;
        MBARRIER_EXPECT_TX(m, KV2_BYTES);
        bulk_g2s(base + 32768 + s * KV2_BYTES,
                 (const char*)Kvp + (size_t)(h * (TT / 64) + 2 * tt) * 32768,
                 KV2_BYTES, m);
    };

    if (tid == 0) {
        MBARRIER_EXPECT_TX(mbq, 32768);
        bulk_g2s(base,         (const char*)Qph + ((size_t)h * TT + q0) * 128, 16384, mbq);
        bulk_g2s(base + 16384, (const char*)Qpl + ((size_t)h * TT + q0) * 128, 16384, mbq);
        issue_kv(0, 0);
        if (1 < ntiles) issue_kv(1, 1);
    }

    MBARRIER_WAIT_PARITY(mbq, 0);
    uint32_t qh[4][4], ql[4][4];
    #pragma unroll
    for (int ks = 0; ks < 4; ks++) {
        uint32_t ro = (uint32_t)(w * 16 + lrow) * 128;
        uint32_t kb = (uint32_t)(ks * 16 + lkof) * 2;
        ldsm_x4(qh[ks][0], qh[ks][1], qh[ks][2], qh[ks][3], base + swz(ro + kb));
        ldsm_x4(ql[ks][0], ql[ks][1], ql[ks][2], ql[ks][3], base + 16384 + swz(ro + kb));
    }

    float o[8][4];
    #pragma unroll
    for (int dt = 0; dt < 8; dt++)
        #pragma unroll
        for (int c = 0; c < 4; c++) o[dt][c] = 0.f;
    float m0 = -INFINITY, m1 = -INFINITY, lp0 = 0.f, lp1 = 0.f;

    const int row0 = q0 + w * 16 + g;
    int ph0 = 0, ph1 = 0;
    int s = 0;

    for (int t = 0; t < ntiles; t++) {
        const int k0 = t << 7;
        if (s == 0) { MBARRIER_WAIT_PARITY(mb0, ph0); ph0 ^= 1; }
        else        { MBARRIER_WAIT_PARITY(mb1, ph1); ph1 ^= 1; }

        uint32_t sb = base + 32768 + s * KV2_BYTES;

        float sc_[16][4];
        #pragma unroll
        for (int nt = 0; nt < 16; nt++)
            #pragma unroll
            for (int c = 0; c < 4; c++) sc_[nt][c] = 0.f;

        #pragma unroll
        for (int ks = 0; ks < 4; ks++) {
            const uint32_t kb = (uint32_t)(ks * 16 + lkof) * 2;
            #pragma unroll
            for (int p = 0; p < 8; p++) {
                uint32_t blk = (uint32_t)(p >> 2) * 32768;
                uint32_t ro = (uint32_t)((p & 3) * 16 + lrow) * 128;
                uint32_t r0, r1, r2, r3, u0, u1, u2, u3;
                ldsm_x4(r0, r1, r2, r3, sb + blk + swz(ro + kb));
                ldsm_x4(u0, u1, u2, u3, sb + blk + 8192 + swz(ro + kb));
                float* s0 = sc_[2 * p];
                float* s1 = sc_[2 * p + 1];
                mma16816(s0[0], s0[1], s0[2], s0[3], qh[ks][0], qh[ks][1], qh[ks][2], qh[ks][3], r0, r2);
                mma16816(s0[0], s0[1], s0[2], s0[3], qh[ks][0], qh[ks][1], qh[ks][2], qh[ks][3], u0, u2);
                mma16816(s0[0], s0[1], s0[2], s0[3], ql[ks][0], ql[ks][1], ql[ks][2], ql[ks][3], r0, r2);
                mma16816(s1[0], s1[1], s1[2], s1[3], qh[ks][0], qh[ks][1], qh[ks][2], qh[ks][3], r1, r3);
                mma16816(s1[0], s1[1], s1[2], s1[3], qh[ks][0], qh[ks][1], qh[ks][2], qh[ks][3], u1, u3);
                mma16816(s1[0], s1[1], s1[2], s1[3], ql[ks][0], ql[ks][1], ql[ks][2], ql[ks][3], r1, r3);
            }
        }

        if (k0 + 128 > q0) {
            #pragma unroll
            for (int nt = 0; nt < 16; nt++) {
                int col = k0 + nt * 8 + 2 * cq;
                if (col     > row0)     sc_[nt][0] = -INFINITY;
                if (col + 1 > row0)     sc_[nt][1] = -INFINITY;
                if (col     > row0 + 8) sc_[nt][2] = -INFINITY;
                if (col + 1 > row0 + 8) sc_[nt][3] = -INFINITY;
            }
        }

        float mx0 = -INFINITY, mx1 = -INFINITY;
        #pragma unroll
        for (int nt = 0; nt < 16; nt++) {
            mx0 = fmaxf(mx0, fmaxf(sc_[nt][0], sc_[nt][1]));
            mx1 = fmaxf(mx1, fmaxf(sc_[nt][2], sc_[nt][3]));
        }
        mx0 = fmaxf(mx0, __shfl_xor_sync(0xffffffffu, mx0, 1));
        mx0 = fmaxf(mx0, __shfl_xor_sync(0xffffffffu, mx0, 2));
        mx1 = fmaxf(mx1, __shfl_xor_sync(0xffffffffu, mx1, 1));
        mx1 = fmaxf(mx1, __shfl_xor_sync(0xffffffffu, mx1, 2));
        float mn0 = fmaxf(m0, mx0), mn1 = fmaxf(m1, mx1);
        float cf0 = fast_exp2(m0 - mn0), cf1 = fast_exp2(m1 - mn1);
        m0 = mn0; m1 = mn1;
        lp0 *= cf0; lp1 *= cf1;
        #pragma unroll
        for (int dt = 0; dt < 8; dt++) {
            o[dt][0] *= cf0; o[dt][1] *= cf0;
            o[dt][2] *= cf1; o[dt][3] *= cf1;
        }

        #pragma unroll
        for (int kk = 0; kk < 8; kk++) {
            float p0 = fast_exp2(sc_[2 * kk][0] - m0);
            float p1 = fast_exp2(sc_[2 * kk][1] - m0);
            float p2 = fast_exp2(sc_[2 * kk][2] - m1);
            float p3 = fast_exp2(sc_[2 * kk][3] - m1);
            float p4 = fast_exp2(sc_[2 * kk + 1][0] - m0);
            float p5 = fast_exp2(sc_[2 * kk + 1][1] - m0);
            float p6 = fast_exp2(sc_[2 * kk + 1][2] - m1);
            float p7 = fast_exp2(sc_[2 * kk + 1][3] - m1);
            lp0 += p0 + p1 + p4 + p5;
            lp1 += p2 + p3 + p6 + p7;
            float h0 = __bfloat162float(__float2bfloat16(p0));
            float h1 = __bfloat162float(__float2bfloat16(p1));
            float h2 = __bfloat162float(__float2bfloat16(p2));
            float h3 = __bfloat162float(__float2bfloat16(p3));
            float h4 = __bfloat162float(__float2bfloat16(p4));
            float h5 = __bfloat162float(__float2bfloat16(p5));
            float h6 = __bfloat162float(__float2bfloat16(p6));
            float h7 = __bfloat162float(__float2bfloat16(p7));
            uint32_t ah0 = pack_bf16x2(h0, h1);
            uint32_t ah1 = pack_bf16x2(h2, h3);
            uint32_t ah2 = pack_bf16x2(h4, h5);
            uint32_t ah3 = pack_bf16x2(h6, h7);
            uint32_t al0 = pack_bf16x2(p0 - h0, p1 - h1);
            uint32_t al1 = pack_bf16x2(p2 - h2, p3 - h3);
            uint32_t al2 = pack_bf16x2(p4 - h4, p5 - h5);
            uint32_t al3 = pack_bf16x2(p6 - h6, p7 - h7);

            uint32_t vblk = (uint32_t)(kk >> 2) * 32768;
            const uint32_t kb = (uint32_t)((kk & 3) * 16 + lkof) * 2;
            #pragma unroll
            for (int dp = 0; dp < 4; dp++) {
                uint32_t ro = (uint32_t)(dp * 16 + lrow) * 128;
                uint32_t v0, v1, v2, v3, x0, x1, x2, x3;
                ldsm_x4(v0, v1, v2, v3, sb + vblk + 16384 + swz(ro + kb));
                ldsm_x4(x0, x1, x2, x3, sb + vblk + 24576 + swz(ro + kb));
                float* oa = o[2 * dp];
                float* ob = o[2 * dp + 1];
                mma16816(oa[0], oa[1], oa[2], oa[3], ah0, ah1, ah2, ah3, v0, v2);
                mma16816(oa[0], oa[1], oa[2], oa[3], ah0, ah1, ah2, ah3, x0, x2);
                mma16816(oa[0], oa[1], oa[2], oa[3], al0, al1, al2, al3, v0, v2);
                mma16816(ob[0], ob[1], ob[2], ob[3], ah0, ah1, ah2, ah3, v1, v3);
                mma16816(ob[0], ob[1], ob[2], ob[3], ah0, ah1, ah2, ah3, x1, x3);
                mma16816(ob[0], ob[1], ob[2], ob[3], al0, al1, al2, al3, v1, v3);
            }
        }
        __syncthreads();
        if (tid == 0 && t + 2 < ntiles) issue_kv(s, t + 2);
        s ^= 1;
    }

    lp0 += __shfl_xor_sync(0xffffffffu, lp0, 1);
    lp0 += __shfl_xor_sync(0xffffffffu, lp0, 2);
    lp1 += __shfl_xor_sync(0xffffffffu, lp1, 1);
    lp1 += __shfl_xor_sync(0xffffffffu, lp1, 2);
    float inv0 = 1.0f / lp0, inv1 = 1.0f / lp1;
    #pragma unroll
    for (int dt = 0; dt < 8; dt++) {
        int col = h * HDIM + dt * 8 + 2 * cq;
        int kc = col >> 5, cin = col & 31;
        float a0 = o[dt][0] * inv0, a1 = o[dt][1] * inv0;
        float b0 = o[dt][2] * inv1, b1 = o[dt][3] * inv1;
        float a0h = __bfloat162float(__float2bfloat16(a0));
        float a1h = __bfloat162float(__float2bfloat16(a1));
        float b0h = __bfloat162float(__float2bfloat16(b0));
        float b1h = __bfloat162float(__float2bfloat16(b1));
        size_t r0b = ((size_t)kc * TT + row0) * 128;
        size_t r1b = ((size_t)kc * TT + row0 + 8) * 128;
        *(uint32_t*)((char*)Ahl + swzs(r0b + (size_t)cin * 2))      = pack_bf16x2(a0h, a1h);
        *(uint32_t*)((char*)Ahl + swzs(r0b + 64 + (size_t)cin * 2)) = pack_bf16x2(a0 - a0h, a1 - a1h);
        *(uint32_t*)((char*)Ahl + swzs(r1b + (size_t)cin * 2))      = pack_bf16x2(b0h, b1h);
        *(uint32_t*)((char*)Ahl + swzs(r1b + 64 + (size_t)cin * 2)) = pack_bf16x2(b0 - b0h, b1 - b1h);
    }
}

// ---------------------------------------------------------------------------
extern "C" void kernel_launch(void* const* d_in, const int* in_sizes, int n_in,
                              void* d_out, int out_size)
{
    const float* x    = (const float*)d_in[0];
    const float* wqkv = (const float*)d_in[1];
    const float* wout = (const float*)d_in[2];
    float* out = (float*)d_out;

    __nv_bfloat16 *xhl, *w1hl, *w2hl, *ahl, *qph, *qpl, *kvp;
    cudaGetSymbolAddress((void**)&xhl,  g_xhl);
    cudaGetSymbolAddress((void**)&w1hl, g_w1hl);
    cudaGetSymbolAddress((void**)&w2hl, g_w2hl);
    cudaGetSymbolAddress((void**)&ahl,  g_ahl);
    cudaGetSymbolAddress((void**)&qph,  g_qph);
    cudaGetSymbolAddress((void**)&qpl,  g_qpl);
    cudaGetSymbolAddress((void**)&kvp,  g_kvp);

    cudaFuncSetAttribute(tc_gemm,     cudaFuncAttributeMaxDynamicSharedMemorySize, GSMEM);
    cudaFuncSetAttribute(tc_gemm_qkv, cudaFuncAttributeMaxDynamicSharedMemorySize, GSMEM_QKV);
    cudaFuncSetAttribute(attn_mma,    cudaFuncAttributeMaxDynamicSharedMemorySize, ASMEM);

    // prep
    split_chunk<<<(TT * DD / 8 + 255) / 256, 256>>>(x, xhl, TT, DD);
    wsplit_chunk<<<dim3(3 * DD / 32, DD / 32), dim3(32, 8)>>>(wqkv, w1hl, DD, 3 * DD);
    wsplit_chunk<<<dim3(DD / 32, DD / 32), dim3(32, 8)>>>(wout, w2hl, DD, DD);

    // 1) QKV projection with fused attention-operand epilogue (kv_pack gone)
    tc_gemm_qkv<<<dim3(3 * DD / 128, TT / 128), 256, GSMEM_QKV>>>(
        xhl, w1hl, qph, qpl, kvp, TT, 3 * DD, DD);

    // 2) causal attention (128-key tiles, 2-stage 64KB ring)
    attn_mma<<<dim3(TT / 128, NH), 256, ASMEM>>>(qph, qpl, kvp, ahl);

    // 3) output projection (round-14 measured-best tc_gemm)
    tc_gemm<<<dim3(DD / 128, TT / 128), 256, GSMEM>>>(ahl, w2hl, out, TT, DD, DD);
}

// round 17
// speedup vs baseline: 1.0790x; 1.0141x over previous
#include <cuda_runtime.h>
#include <cuda_bf16.h>
#include <math.h>
#include <stdint.h>

#define TT 4096
#define DD 1024
#define NH 16
#define HDIM 64

// ---------------------------------------------------------------------------
// Scratch (allocation-free rule: device globals). 16B-aligned.
// GEMM operands chunk-major hi/lo interleaved, SW128-preswizzled:
//   [kc][row][32 hi bf16 | 32 lo bf16] (128B rows, kc = K/32)
// Attention: Q preswizzled rows [h][t][64] hi/lo; K/V packed per
// (head, 64-key tile) as one 32KB block: Kh|Kl|Vth|Vtl (8KB each).
// Two consecutive blocks form one 64KB 128-key stage.
// ---------------------------------------------------------------------------
__device__ __align__(16) __nv_bfloat16 g_xhl[(size_t)TT * DD * 2];
__device__ __align__(16) __nv_bfloat16 g_w1hl[(size_t)3 * DD * DD * 2];
__device__ __align__(16) __nv_bfloat16 g_w2hl[(size_t)DD * DD * 2];
__device__ __align__(16) __nv_bfloat16 g_ahl[(size_t)TT * DD * 2];
__device__ __align__(16) __nv_bfloat16 g_qph[(size_t)NH * TT * HDIM];
__device__ __align__(16) __nv_bfloat16 g_qpl[(size_t)NH * TT * HDIM];
__device__ __align__(16) __nv_bfloat16 g_kvp[(size_t)NH * (TT / 64) * 16384]; // 32MB

// ---------------------------------------------------------------------------
// PTX helpers
// ---------------------------------------------------------------------------
__device__ __forceinline__ uint32_t smem_u32(const void* p) {
    uint32_t a;
    asm("{ .reg .u64 t; cvta.to.shared.u64 t, %1; cvt.u32.u64 %0, t; }" : "=r"(a) : "l"(p));
    return a;
}
__device__ __forceinline__ void ldsm_x4(uint32_t& r0, uint32_t& r1, uint32_t& r2, uint32_t& r3,
                                        uint32_t addr) {
    asm volatile("ldmatrix.sync.aligned.m8n8.x4.shared.b16 {%0,%1,%2,%3}, [%4];"
                 : "=r"(r0), "=r"(r1), "=r"(r2), "=r"(r3) : "r"(addr));
}
__device__ __forceinline__ void mma16816(float& c0, float& c1, float& c2, float& c3,
                                         uint32_t a0, uint32_t a1, uint32_t a2, uint32_t a3,
                                         uint32_t b0, uint32_t b1) {
    asm("mma.sync.aligned.m16n8k16.row.col.f32.bf16.bf16.f32 "
        "{%0,%1,%2,%3}, {%4,%5,%6,%7}, {%8,%9}, {%0,%1,%2,%3};"
        : "+f"(c0), "+f"(c1), "+f"(c2), "+f"(c3)
        : "r"(a0), "r"(a1), "r"(a2), "r"(a3), "r"(b0), "r"(b1));
}
__device__ __forceinline__ void bulk_g2s(uint32_t dst, const void* src, uint32_t bytes,
                                         uint32_t mbar) {
    asm volatile("cp.async.bulk.shared::cluster.global.mbarrier::complete_tx::bytes "
                 "[%0], [%1], %2, [%3];"
                 :: "r"(dst), "l"(src), "r"(bytes), "r"(mbar) : "memory");
}
#define MBARRIER_INIT(mb, c) \
    asm volatile("mbarrier.init.shared.b64 [%0], %1;" :: "r"((uint32_t)(mb)), "r"((uint32_t)(c)) : "memory")
#define MBARRIER_EXPECT_TX(mb, bytes) \
    asm volatile("mbarrier.arrive.expect_tx.shared.b64 _, [%0], %1;" \
                 :: "r"((uint32_t)(mb)), "r"((uint32_t)(bytes)) : "memory")
#define MBARRIER_WAIT_PARITY(mb, ph) do { \
    uint32_t _m = (uint32_t)(mb), _p = (uint32_t)(ph), _d; \
    asm volatile("{ .reg .pred p; mbarrier.try_wait.parity.acquire.cta.shared::cta.b64 p, [%1], %2; " \
                 "selp.b32 %0, 1, 0, p; }" : "=r"(_d) : "r"(_m), "r"(_p) : "memory"); \
    if (!_d) { \
        asm volatile("{ .reg .pred P1; WL_%=: mbarrier.try_wait.parity.acquire.cta.shared::cta.b64 P1, [%0], %1, 0x989680; " \
                     "@P1 bra.uni WD_%=; bra.uni WL_%=; WD_%=: }" :: "r"(_m), "r"(_p) : "memory"); \
    } \
} while (0)

__device__ __forceinline__ float fast_exp2(float x) {
    float y;
    asm("ex2.approx.ftz.f32 %0, %1;" : "=f"(y) : "f"(x));
    return y;
}
__device__ __forceinline__ uint32_t pack_bf16x2(float a, float b) {
    __nv_bfloat162 t = __floats2bfloat162_rn(a, b);
    return *reinterpret_cast<uint32_t*>(&t);
}
__device__ __forceinline__ uint32_t swz(uint32_t o)  { return o ^ ((o >> 3) & 0x70); }
__device__ __forceinline__ size_t   swzs(size_t o)   { return o ^ ((o >> 3) & 0x70); }

__device__ __forceinline__ void split16(const float (&f)[16],
                                        uint4& h0, uint4& h1, uint4& l0, uint4& l1)
{
    float hh[16];
    #pragma unroll
    for (int i = 0; i < 16; i++) hh[i] = __bfloat162float(__float2bfloat16(f[i]));
    h0 = make_uint4(pack_bf16x2(hh[0], hh[1]),  pack_bf16x2(hh[2], hh[3]),
                    pack_bf16x2(hh[4], hh[5]),  pack_bf16x2(hh[6], hh[7]));
    h1 = make_uint4(pack_bf16x2(hh[8], hh[9]),  pack_bf16x2(hh[10], hh[11]),
                    pack_bf16x2(hh[12], hh[13]), pack_bf16x2(hh[14], hh[15]));
    l0 = make_uint4(pack_bf16x2(f[0]-hh[0], f[1]-hh[1]),   pack_bf16x2(f[2]-hh[2], f[3]-hh[3]),
                    pack_bf16x2(f[4]-hh[4], f[5]-hh[5]),   pack_bf16x2(f[6]-hh[6], f[7]-hh[7]));
    l1 = make_uint4(pack_bf16x2(f[8]-hh[8], f[9]-hh[9]),   pack_bf16x2(f[10]-hh[10], f[11]-hh[11]),
                    pack_bf16x2(f[12]-hh[12], f[13]-hh[13]), pack_bf16x2(f[14]-hh[14], f[15]-hh[15]));
}

// ---------------------------------------------------------------------------
// prep_all: ONE launch covering all three independent prep jobs (co-resident
// instead of three serialized small launches).
//   blocks [0, 2048):        x fp32 [TT][DD]      -> xhl chunk-major hi/lo
//   blocks [2048, 5120):     wqkv fp32 [DD][3DD]  -> w1hl wT chunk-major
//   blocks [5120, 6144):     wout fp32 [DD][DD]   -> w2hl wT chunk-major
// 256 threads; wsplit parts map (32,8) onto flat tid.
// ---------------------------------------------------------------------------
__global__ __launch_bounds__(256) void prep_all(
    const float* __restrict__ x, const float* __restrict__ wqkv,
    const float* __restrict__ wout,
    __nv_bfloat16* __restrict__ xhl, __nv_bfloat16* __restrict__ w1hl,
    __nv_bfloat16* __restrict__ w2hl)
{
    const int b = blockIdx.x;
    const int tid = threadIdx.x;

    if (b < 2048) {
        // ---- split_chunk(x): M=TT, K=DD; 8 elems per thread
        const int M = TT, K = DD;
        size_t i8 = ((size_t)b * 256 + tid) * 8;
        int m  = (int)(i8 / K);
        int k  = (int)(i8 % K);
        int kc = k >> 5, kin = k & 31;
        float4 v0 = *(const float4*)(x + i8);
        float4 v1 = *(const float4*)(x + i8 + 4);
        float f[8] = {v0.x, v0.y, v0.z, v0.w, v1.x, v1.y, v1.z, v1.w};
        float h[8];
        #pragma unroll
        for (int j = 0; j < 8; j++) h[j] = __bfloat162float(__float2bfloat16(f[j]));
        uint4 hu, lu;
        hu.x = pack_bf16x2(h[0], h[1]); hu.y = pack_bf16x2(h[2], h[3]);
        hu.z = pack_bf16x2(h[4], h[5]); hu.w = pack_bf16x2(h[6], h[7]);
        lu.x = pack_bf16x2(f[0]-h[0], f[1]-h[1]); lu.y = pack_bf16x2(f[2]-h[2], f[3]-h[3]);
        lu.z = pack_bf16x2(f[4]-h[4], f[5]-h[5]); lu.w = pack_bf16x2(f[6]-h[6], f[7]-h[7]);
        size_t rowb = ((size_t)kc * M + m) * 128;
        *(uint4*)((char*)xhl + swzs(rowb + (size_t)kin * 2))      = hu;
        *(uint4*)((char*)xhl + swzs(rowb + 64 + (size_t)kin * 2)) = lu;
        return;
    }

    // ---- wsplit_chunk part: transpose 32x32 fp32 tile + split
    __shared__ float t[32][33];
    const float* w;
    __nv_bfloat16* o;
    int K, N, bxx, byy;
    if (b < 5120) {
        w = wqkv; o = w1hl; K = DD; N = 3 * DD;
        int idx = b - 2048;                 // 0..3071, (N/32=96) x (K/32=32)
        bxx = idx % 96; byy = idx / 96;
    } else {
        w = wout; o = w2hl; K = DD; N = DD;
        int idx = b - 5120;                 // 0..1023, 32 x 32
        bxx = idx % 32; byy = idx / 32;
    }
    const int n0 = bxx * 32, k0 = byy * 32;
    const int tx = tid & 31, ty = tid >> 5;

    for (int j = ty; j < 32; j += 8)
        t[j][tx] = w[(size_t)(k0 + j) * N + n0 + tx];
    __syncthreads();
    float f0 = t[ty * 4 + 0][tx], f1 = t[ty * 4 + 1][tx];
    float f2 = t[ty * 4 + 2][tx], f3 = t[ty * 4 + 3][tx];
    float h0 = __bfloat162float(__float2bfloat16(f0));
    float h1 = __bfloat162float(__float2bfloat16(f1));
    float h2 = __bfloat162float(__float2bfloat16(f2));
    float h3 = __bfloat162float(__float2bfloat16(f3));
    uint2 hu, lu;
    hu.x = pack_bf16x2(h0, h1); hu.y = pack_bf16x2(h2, h3);
    lu.x = pack_bf16x2(f0 - h0, f1 - h1); lu.y = pack_bf16x2(f2 - h2, f3 - h3);
    size_t rowb = ((size_t)byy * N + n0 + tx) * 128;
    *(uint2*)((char*)o + swzs(rowb + (size_t)ty * 8))      = hu;
    *(uint2*)((char*)o + swzs(rowb + 64 + (size_t)ty * 8)) = lu;
}

// ---------------------------------------------------------------------------
// mma.sync bf16 split GEMM (round-14 measured-best form): 2-stage bulk
// pipeline, per-chunk __syncthreads. fp32 output. (unchanged)
// ---------------------------------------------------------------------------
#define CH_BYTES 16384
#define STG_BYTES (2 * CH_BYTES)
#define GSMEM (2 * STG_BYTES)        // 65536

__global__ __launch_bounds__(256, 2) void tc_gemm(
    const __nv_bfloat16* __restrict__ Ahl, const __nv_bfloat16* __restrict__ Bhl,
    float* __restrict__ C, int M, int N, int K)
{
    extern __shared__ __align__(1024) char dsm[];
    __shared__ __align__(8) uint64_t mbar_s[2];
    const uint32_t base = smem_u32(dsm);

    const int tid  = threadIdx.x;
    const int wid  = tid >> 5;
    const int lane = tid & 31;
    const int wm   = wid >> 2;
    const int wn   = wid & 3;
    const int bm   = blockIdx.y * 128, bn = blockIdx.x * 128;
    const int lrow = (lane & 7) + ((lane >> 3) & 1) * 8;
    const int lkof = (lane >> 4) * 8;

    if (tid == 0) {
        MBARRIER_INIT(smem_u32(&mbar_s[0]), 1);
        MBARRIER_INIT(smem_u32(&mbar_s[1]), 1);
    }
    __syncthreads();
    uint32_t mb0 = smem_u32(&mbar_s[0]);
    uint32_t mb1 = smem_u32(&mbar_s[1]);

    const int NCH = K / 32;

    auto issue = [&](int s, int t) {
        uint32_t m = s ? mb1 : mb0;
        MBARRIER_EXPECT_TX(m, STG_BYTES);
        const char* srcA = (const char*)Ahl + ((size_t)t * M + bm) * 128;
        const char* srcB = (const char*)Bhl + ((size_t)t * N + bn) * 128;
        uint32_t d = base + s * STG_BYTES;
        bulk_g2s(d,            srcA, CH_BYTES, m);
        bulk_g2s(d + CH_BYTES, srcB, CH_BYTES, m);
    };
    if (tid == 0) {
        issue(0, 0);
        if (NCH > 1) issue(1, 1);
    }

    float acc[4][4][4];
    #pragma unroll
    for (int mt = 0; mt < 4; mt++)
        #pragma unroll
        for (int nt = 0; nt < 4; nt++)
            #pragma unroll
            for (int c = 0; c < 4; c++) acc[mt][nt][c] = 0.f;

    int ph0 = 0, ph1 = 0;

    for (int t = 0; t < NCH; t++) {
        int s = t & 1;
        if (s == 0) { MBARRIER_WAIT_PARITY(mb0, ph0); ph0 ^= 1; }
        else        { MBARRIER_WAIT_PARITY(mb1, ph1); ph1 ^= 1; }

        uint32_t aB = base + s * STG_BYTES;
        uint32_t bB = aB + CH_BYTES;

        #pragma unroll
        for (int ks = 0; ks < 2; ks++) {
            const uint32_t kb = (uint32_t)(ks * 16 + lkof) * 2;

            uint32_t bh[4][2], bl[4][2];
            #pragma unroll
            for (int p = 0; p < 2; p++) {
                uint32_t ro = (uint32_t)(wn * 32 + p * 16 + lrow) * 128;
                uint32_t r0, r1, r2, r3;
                ldsm_x4(r0, r1, r2, r3, bB + swz(ro + kb));
                bh[p * 2][0] = r0; bh[p * 2][1] = r2;
                bh[p * 2 + 1][0] = r1; bh[p * 2 + 1][1] = r3;
                ldsm_x4(r0, r1, r2, r3, bB + swz(ro + 64 + kb));
                bl[p * 2][0] = r0; bl[p * 2][1] = r2;
                bl[p * 2 + 1][0] = r1; bl[p * 2 + 1][1] = r3;
            }

            #pragma unroll
            for (int mt = 0; mt < 4; mt++) {
                uint32_t ro = (uint32_t)(wm * 64 + mt * 16 + lrow) * 128;
                uint32_t ah0, ah1, ah2, ah3, al0, al1, al2, al3;
                ldsm_x4(ah0, ah1, ah2, ah3, aB + swz(ro + kb));
                ldsm_x4(al0, al1, al2, al3, aB + swz(ro + 64 + kb));
                #pragma unroll
                for (int nt = 0; nt < 4; nt++) {
                    float* c = acc[mt][nt];
                    mma16816(c[0], c[1], c[2], c[3], ah0, ah1, ah2, ah3,
                             bh[nt][0], bh[nt][1]);
                    mma16816(c[0], c[1], c[2], c[3], ah0, ah1, ah2, ah3,
                             bl[nt][0], bl[nt][1]);
                    mma16816(c[0], c[1], c[2], c[3], al0, al1, al2, al3,
                             bh[nt][0], bh[nt][1]);
                }
            }
        }
        __syncthreads();
        if (tid == 0 && t + 2 < NCH) issue(s, t + 2);
    }

    const int g  = lane >> 2;
    const int tg = lane & 3;
    #pragma unroll
    for (int mt = 0; mt < 4; mt++) {
        #pragma unroll
        for (int nt = 0; nt < 4; nt++) {
            int row = bm + wm * 64 + mt * 16 + g;
            int col = bn + wn * 32 + nt * 8 + tg * 2;
            float* c = acc[mt][nt];
            *(float2*)(C + (size_t)row * N + col)       = make_float2(c[0], c[1]);
            *(float2*)(C + (size_t)(row + 8) * N + col) = make_float2(c[2], c[3]);
        }
    }
}

// ---------------------------------------------------------------------------
// tc_gemm_qkv (round-16 form, unchanged): fused attention-operand epilogue.
// ---------------------------------------------------------------------------
#define VPITCH 132
#define GSMEM_QKV (VPITCH * 128 * 4)   // 67584

__global__ __launch_bounds__(256, 2) void tc_gemm_qkv(
    const __nv_bfloat16* __restrict__ Ahl, const __nv_bfloat16* __restrict__ Bhl,
    __nv_bfloat16* __restrict__ Qph, __nv_bfloat16* __restrict__ Qpl,
    __nv_bfloat16* __restrict__ Kvp, int M, int N, int K)
{
    extern __shared__ __align__(1024) char dsm[];
    __shared__ __align__(8) uint64_t mbar_s[2];
    const uint32_t base = smem_u32(dsm);

    const int tid  = threadIdx.x;
    const int wid  = tid >> 5;
    const int lane = tid & 31;
    const int wm   = wid >> 2;
    const int wn   = wid & 3;
    const int bm   = blockIdx.y * 128, bn = blockIdx.x * 128;
    const int lrow = (lane & 7) + ((lane >> 3) & 1) * 8;
    const int lkof = (lane >> 4) * 8;

    if (tid == 0) {
        MBARRIER_INIT(smem_u32(&mbar_s[0]), 1);
        MBARRIER_INIT(smem_u32(&mbar_s[1]), 1);
    }
    __syncthreads();
    uint32_t mb0 = smem_u32(&mbar_s[0]);
    uint32_t mb1 = smem_u32(&mbar_s[1]);

    const int NCH = K / 32;

    auto issue = [&](int s, int t) {
        uint32_t m = s ? mb1 : mb0;
        MBARRIER_EXPECT_TX(m, STG_BYTES);
        const char* srcA = (const char*)Ahl + ((size_t)t * M + bm) * 128;
        const char* srcB = (const char*)Bhl + ((size_t)t * N + bn) * 128;
        uint32_t d = base + s * STG_BYTES;
        bulk_g2s(d,            srcA, CH_BYTES, m);
        bulk_g2s(d + CH_BYTES, srcB, CH_BYTES, m);
    };
    if (tid == 0) {
        issue(0, 0);
        if (NCH > 1) issue(1, 1);
    }

    float acc[4][4][4];
    #pragma unroll
    for (int mt = 0; mt < 4; mt++)
        #pragma unroll
        for (int nt = 0; nt < 4; nt++)
            #pragma unroll
            for (int c = 0; c < 4; c++) acc[mt][nt][c] = 0.f;

    int ph0 = 0, ph1 = 0;

    for (int t = 0; t < NCH; t++) {
        int s = t & 1;
        if (s == 0) { MBARRIER_WAIT_PARITY(mb0, ph0); ph0 ^= 1; }
        else        { MBARRIER_WAIT_PARITY(mb1, ph1); ph1 ^= 1; }

        uint32_t aB = base + s * STG_BYTES;
        uint32_t bB = aB + CH_BYTES;

        #pragma unroll
        for (int ks = 0; ks < 2; ks++) {
            const uint32_t kb = (uint32_t)(ks * 16 + lkof) * 2;

            uint32_t bh[4][2], bl[4][2];
            #pragma unroll
            for (int p = 0; p < 2; p++) {
                uint32_t ro = (uint32_t)(wn * 32 + p * 16 + lrow) * 128;
                uint32_t r0, r1, r2, r3;
                ldsm_x4(r0, r1, r2, r3, bB + swz(ro + kb));
                bh[p * 2][0] = r0; bh[p * 2][1] = r2;
                bh[p * 2 + 1][0] = r1; bh[p * 2 + 1][1] = r3;
                ldsm_x4(r0, r1, r2, r3, bB + swz(ro + 64 + kb));
                bl[p * 2][0] = r0; bl[p * 2][1] = r2;
                bl[p * 2 + 1][0] = r1; bl[p * 2 + 1][1] = r3;
            }

            #pragma unroll
            for (int mt = 0; mt < 4; mt++) {
                uint32_t ro = (uint32_t)(wm * 64 + mt * 16 + lrow) * 128;
                uint32_t ah0, ah1, ah2, ah3, al0, al1, al2, al3;
                ldsm_x4(ah0, ah1, ah2, ah3, aB + swz(ro + kb));
                ldsm_x4(al0, al1, al2, al3, aB + swz(ro + 64 + kb));
                #pragma unroll
                for (int nt = 0; nt < 4; nt++) {
                    float* c = acc[mt][nt];
                    mma16816(c[0], c[1], c[2], c[3], ah0, ah1, ah2, ah3,
                             bh[nt][0], bh[nt][1]);
                    mma16816(c[0], c[1], c[2], c[3], ah0, ah1, ah2, ah3,
                             bl[nt][0], bl[nt][1]);
                    mma16816(c[0], c[1], c[2], c[3], al0, al1, al2, al3,
                             bh[nt][0], bh[nt][1]);
                }
            }
        }
        __syncthreads();
        if (tid == 0 && t + 2 < NCH) issue(s, t + 2);
    }

    const int g  = lane >> 2;
    const int tg = lane & 3;
    const int region = bn >> 10;          // 0=Q, 1=K, 2=V
    const int cb = bn & 1023;
    const float sc = 0.125f * 1.4426950408889634f;

    if (region == 0) {
        #pragma unroll
        for (int mt = 0; mt < 4; mt++) {
            #pragma unroll
            for (int nt = 0; nt < 4; nt++) {
                int lc = cb + wn * 32 + nt * 8 + tg * 2;
                int hh = lc >> 6, d = lc & 63;
                float* c = acc[mt][nt];
                #pragma unroll
                for (int half = 0; half < 2; half++) {
                    int trow = bm + wm * 64 + mt * 16 + g + half * 8;
                    float a0 = c[2 * half] * sc, a1 = c[2 * half + 1] * sc;
                    float h0 = __bfloat162float(__float2bfloat16(a0));
                    float h1 = __bfloat162float(__float2bfloat16(a1));
                    size_t rb = ((size_t)hh * TT + trow) * 128 + (size_t)d * 2;
                    *(uint32_t*)((char*)Qph + swzs(rb)) = pack_bf16x2(h0, h1);
                    *(uint32_t*)((char*)Qpl + swzs(rb)) = pack_bf16x2(a0 - h0, a1 - h1);
                }
            }
        }
    } else if (region == 1) {
        #pragma unroll
        for (int mt = 0; mt < 4; mt++) {
            #pragma unroll
            for (int nt = 0; nt < 4; nt++) {
                int lc = cb + wn * 32 + nt * 8 + tg * 2;
                int hh = lc >> 6, d = lc & 63;
                float* c = acc[mt][nt];
                #pragma unroll
                for (int half = 0; half < 2; half++) {
                    int trow = bm + wm * 64 + mt * 16 + g + half * 8;
                    float a0 = c[2 * half], a1 = c[2 * half + 1];
                    float h0 = __bfloat162float(__float2bfloat16(a0));
                    float h1 = __bfloat162float(__float2bfloat16(a1));
                    size_t kvb = (size_t)(hh * (TT / 64) + (trow >> 6)) * 32768;
                    size_t kr  = (size_t)(trow & 63) * 128 + (size_t)d * 2;
                    *(uint32_t*)((char*)Kvp + kvb + swzs(kr))        = pack_bf16x2(h0, h1);
                    *(uint32_t*)((char*)Kvp + kvb + 8192 + swzs(kr)) = pack_bf16x2(a0 - h0, a1 - h1);
                }
            }
        }
    } else {
        float* vsm = (float*)dsm;
        #pragma unroll
        for (int mt = 0; mt < 4; mt++) {
            #pragma unroll
            for (int nt = 0; nt < 4; nt++) {
                int rl = wm * 64 + mt * 16 + g;
                int cl = wn * 32 + nt * 8 + tg * 2;
                float* c = acc[mt][nt];
                vsm[rl * VPITCH + cl]           = c[0];
                vsm[rl * VPITCH + cl + 1]       = c[1];
                vsm[(rl + 8) * VPITCH + cl]     = c[2];
                vsm[(rl + 8) * VPITCH + cl + 1] = c[3];
            }
        }
        __syncthreads();
        const int d  = tid >> 2;
        const int c0 = (tid & 3) * 16;
        #pragma unroll
        for (int b = 0; b < 2; b++) {
            #pragma unroll
            for (int hhp = 0; hhp < 2; hhp++) {
                int hh = (cb >> 6) + hhp;
                size_t kvb = (size_t)(hh * (TT / 64) + (bm >> 6) + b) * 32768;
                float vf[16];
                #pragma unroll
                for (int i = 0; i < 16; i++)
                    vf[i] = vsm[(64 * b + c0 + i) * VPITCH + 64 * hhp + d];
                uint4 h0, h1, l0, l1;
                split16(vf, h0, h1, l0, l1);
                size_t vr = (size_t)d * 128 + (size_t)c0 * 2;
                *(uint4*)((char*)Kvp + kvb + 16384 + swzs(vr))      = h0;
                *(uint4*)((char*)Kvp + kvb + 16384 + swzs(vr + 16)) = h1;
                *(uint4*)((char*)Kvp + kvb + 24576 + swzs(vr))      = l0;
                *(uint4*)((char*)Kvp + kvb + 24576 + swzs(vr + 16)) = l1;
            }
        }
    }
}

// ---------------------------------------------------------------------------
// Flash attention (round-14 form, unchanged): mma.sync bf16 split, 128-key
// tiles, 2-stage 64KB ring, 1 CTA/SM, fused split epilogue.
// ---------------------------------------------------------------------------
#define KV2_BYTES 65536
#define ASMEM (32768 + 2 * KV2_BYTES)   // 163840

__global__ __launch_bounds__(256, 1) void attn_mma(
    const __nv_bfloat16* __restrict__ Qph, const __nv_bfloat16* __restrict__ Qpl,
    const __nv_bfloat16* __restrict__ Kvp, __nv_bfloat16* __restrict__ Ahl)
{
    extern __shared__ __align__(1024) char asmem[];
    __shared__ __align__(8) uint64_t mbar_s[3];
    const uint32_t base = smem_u32(asmem);

    const int h   = blockIdx.y;
    const int bx  = (gridDim.x - 1) - blockIdx.x;   // heavy blocks first
    const int q0  = bx * 128;
    const int tid = threadIdx.x;
    const int w   = tid >> 5;
    const int lane = tid & 31;
    const int g   = lane >> 2;
    const int cq  = lane & 3;
    const int lrow = (lane & 7) + ((lane >> 3) & 1) * 8;
    const int lkof = (lane >> 4) * 8;
    const int ntiles = (q0 + 128) >> 7;

    if (tid == 0) {
        #pragma unroll
        for (int j = 0; j < 3; j++) MBARRIER_INIT(smem_u32(&mbar_s[j]), 1);
    }
    __syncthreads();
    uint32_t mb0 = smem_u32(&mbar_s[0]);
    uint32_t mb1 = smem_u32(&mbar_s[1]);
    uint32_t mbq = smem_u32(&mbar_s[2]);

    auto issue_kv = [&](int s, int tt) {
        uint32_t m = (s == 0) ? mb0 : mb1;
        MBARRIER_EXPECT_TX(m, KV2_BYTES);
        bulk_g2s(base + 32768 + s * KV2_BYTES,
                 (const char*)Kvp + (size_t)(h * (TT / 64) + 2 * tt) * 32768,
                 KV2_BYTES, m);
    };

    if (tid == 0) {
        MBARRIER_EXPECT_TX(mbq, 32768);
        bulk_g2s(base,         (const char*)Qph + ((size_t)h * TT + q0) * 128, 16384, mbq);
        bulk_g2s(base + 16384, (const char*)Qpl + ((size_t)h * TT + q0) * 128, 16384, mbq);
        issue_kv(0, 0);
        if (1 < ntiles) issue_kv(1, 1);
    }

    MBARRIER_WAIT_PARITY(mbq, 0);
    uint32_t qh[4][4], ql[4][4];
    #pragma unroll
    for (int ks = 0; ks < 4; ks++) {
        uint32_t ro = (uint32_t)(w * 16 + lrow) * 128;
        uint32_t kb = (uint32_t)(ks * 16 + lkof) * 2;
        ldsm_x4(qh[ks][0], qh[ks][1], qh[ks][2], qh[ks][3], base + swz(ro + kb));
        ldsm_x4(ql[ks][0], ql[ks][1], ql[ks][2], ql[ks][3], base + 16384 + swz(ro + kb));
    }

    float o[8][4];
    #pragma unroll
    for (int dt = 0; dt < 8; dt++)
        #pragma unroll
        for (int c = 0; c < 4; c++) o[dt][c] = 0.f;
    float m0 = -INFINITY, m1 = -INFINITY, lp0 = 0.f, lp1 = 0.f;

    const int row0 = q0 + w * 16 + g;
    int ph0 = 0, ph1 = 0;
    int s = 0;

    for (int t = 0; t < ntiles; t++) {
        const int k0 = t << 7;
        if (s == 0) { MBARRIER_WAIT_PARITY(mb0, ph0); ph0 ^= 1; }
        else        { MBARRIER_WAIT_PARITY(mb1, ph1); ph1 ^= 1; }

        uint32_t sb = base + 32768 + s * KV2_BYTES;

        float sc_[16][4];
        #pragma unroll
        for (int nt = 0; nt < 16; nt++)
            #pragma unroll
            for (int c = 0; c < 4; c++) sc_[nt][c] = 0.f;

        #pragma unroll
        for (int ks = 0; ks < 4; ks++) {
            const uint32_t kb = (uint32_t)(ks * 16 + lkof) * 2;
            #pragma unroll
            for (int p = 0; p < 8; p++) {
                uint32_t blk = (uint32_t)(p >> 2) * 32768;
                uint32_t ro = (uint32_t)((p & 3) * 16 + lrow) * 128;
                uint32_t r0, r1, r2, r3, u0, u1, u2, u3;
                ldsm_x4(r0, r1, r2, r3, sb + blk + swz(ro + kb));
                ldsm_x4(u0, u1, u2, u3, sb + blk + 8192 + swz(ro + kb));
                float* s0 = sc_[2 * p];
                float* s1 = sc_[2 * p + 1];
                mma16816(s0[0], s0[1], s0[2], s0[3], qh[ks][0], qh[ks][1], qh[ks][2], qh[ks][3], r0, r2);
                mma16816(s0[0], s0[1], s0[2], s0[3], qh[ks][0], qh[ks][1], qh[ks][2], qh[ks][3], u0, u2);
                mma16816(s0[0], s0[1], s0[2], s0[3], ql[ks][0], ql[ks][1], ql[ks][2], ql[ks][3], r0, r2);
                mma16816(s1[0], s1[1], s1[2], s1[3], qh[ks][0], qh[ks][1], qh[ks][2], qh[ks][3], r1, r3);
                mma16816(s1[0], s1[1], s1[2], s1[3], qh[ks][0], qh[ks][1], qh[ks][2], qh[ks][3], u1, u3);
                mma16816(s1[0], s1[1], s1[2], s1[3], ql[ks][0], ql[ks][1], ql[ks][2], ql[ks][3], r1, r3);
            }
        }

        if (k0 + 128 > q0) {
            #pragma unroll
            for (int nt = 0; nt < 16; nt++) {
                int col = k0 + nt * 8 + 2 * cq;
                if (col     > row0)     sc_[nt][0] = -INFINITY;
                if (col + 1 > row0)     sc_[nt][1] = -INFINITY;
                if (col     > row0 + 8) sc_[nt][2] = -INFINITY;
                if (col + 1 > row0 + 8) sc_[nt][3] = -INFINITY;
            }
        }

        float mx0 = -INFINITY, mx1 = -INFINITY;
        #pragma unroll
        for (int nt = 0; nt < 16; nt++) {
            mx0 = fmaxf(mx0, fmaxf(sc_[nt][0], sc_[nt][1]));
            mx1 = fmaxf(mx1, fmaxf(sc_[nt][2], sc_[nt][3]));
        }
        mx0 = fmaxf(mx0, __shfl_xor_sync(0xffffffffu, mx0, 1));
        mx0 = fmaxf(mx0, __shfl_xor_sync(0xffffffffu, mx0, 2));
        mx1 = fmaxf(mx1, __shfl_xor_sync(0xffffffffu, mx1, 1));
        mx1 = fmaxf(mx1, __shfl_xor_sync(0xffffffffu, mx1, 2));
        float mn0 = fmaxf(m0, mx0), mn1 = fmaxf(m1, mx1);
        float cf0 = fast_exp2(m0 - mn0), cf1 = fast_exp2(m1 - mn1);
        m0 = mn0; m1 = mn1;
        lp0 *= cf0; lp1 *= cf1;
        #pragma unroll
        for (int dt = 0; dt < 8; dt++) {
            o[dt][0] *= cf0; o[dt][1] *= cf0;
            o[dt][2] *= cf1; o[dt][3] *= cf1;
        }

        #pragma unroll
        for (int kk = 0; kk < 8; kk++) {
            float p0 = fast_exp2(sc_[2 * kk][0] - m0);
            float p1 = fast_exp2(sc_[2 * kk][1] - m0);
            float p2 = fast_exp2(sc_[2 * kk][2] - m1);
            float p3 = fast_exp2(sc_[2 * kk][3] - m1);
            float p4 = fast_exp2(sc_[2 * kk + 1][0] - m0);
            float p5 = fast_exp2(sc_[2 * kk + 1][1] - m0);
            float p6 = fast_exp2(sc_[2 * kk + 1][2] - m1);
            float p7 = fast_exp2(sc_[2 * kk + 1][3] - m1);
            lp0 += p0 + p1 + p4 + p5;
            lp1 += p2 + p3 + p6 + p7;
            float h0 = __bfloat162float(__float2bfloat16(p0));
            float h1 = __bfloat162float(__float2bfloat16(p1));
            float h2 = __bfloat162float(__float2bfloat16(p2));
            float h3 = __bfloat162float(__float2bfloat16(p3));
            float h4 = __bfloat162float(__float2bfloat16(p4));
            float h5 = __bfloat162float(__float2bfloat16(p5));
            float h6 = __bfloat162float(__float2bfloat16(p6));
            float h7 = __bfloat162float(__float2bfloat16(p7));
            uint32_t ah0 = pack_bf16x2(h0, h1);
            uint32_t ah1 = pack_bf16x2(h2, h3);
            uint32_t ah2 = pack_bf16x2(h4, h5);
            uint32_t ah3 = pack_bf16x2(h6, h7);
            uint32_t al0 = pack_bf16x2(p0 - h0, p1 - h1);
            uint32_t al1 = pack_bf16x2(p2 - h2, p3 - h3);
            uint32_t al2 = pack_bf16x2(p4 - h4, p5 - h5);
            uint32_t al3 = pack_bf16x2(p6 - h6, p7 - h7);

            uint32_t vblk = (uint32_t)(kk >> 2) * 32768;
            const uint32_t kb = (uint32_t)((kk & 3) * 16 + lkof) * 2;
            #pragma unroll
            for (int dp = 0; dp < 4; dp++) {
                uint32_t ro = (uint32_t)(dp * 16 + lrow) * 128;
                uint32_t v0, v1, v2, v3, x0, x1, x2, x3;
                ldsm_x4(v0, v1, v2, v3, sb + vblk + 16384 + swz(ro + kb));
                ldsm_x4(x0, x1, x2, x3, sb + vblk + 24576 + swz(ro + kb));
                float* oa = o[2 * dp];
                float* ob = o[2 * dp + 1];
                mma16816(oa[0], oa[1], oa[2], oa[3], ah0, ah1, ah2, ah3, v0, v2);
                mma16816(oa[0], oa[1], oa[2], oa[3], ah0, ah1, ah2, ah3, x0, x2);
                mma16816(oa[0], oa[1], oa[2], oa[3], al0, al1, al2, al3, v0, v2);
                mma16816(ob[0], ob[1], ob[2], ob[3], ah0, ah1, ah2, ah3, v1, v3);
                mma16816(ob[0], ob[1], ob[2], ob[3], ah0, ah1, ah2, ah3, x1, x3);
                mma16816(ob[0], ob[1], ob[2], ob[3], al0, al1, al2, al3, v1, v3);
            }
        }
        __syncthreads();
        if (tid == 0 && t + 2 < ntiles) issue_kv(s, t + 2);
        s ^= 1;
    }

    lp0 += __shfl_xor_sync(0xffffffffu, lp0, 1);
    lp0 += __shfl_xor_sync(0xffffffffu, lp0, 2);
    lp1 += __shfl_xor_sync(0xffffffffu, lp1, 1);
    lp1 += __shfl_xor_sync(0xffffffffu, lp1, 2);
    float inv0 = 1.0f / lp0, inv1 = 1.0f / lp1;
    #pragma unroll
    for (int dt = 0; dt < 8; dt++) {
        int col = h * HDIM + dt * 8 + 2 * cq;
        int kc = col >> 5, cin = col & 31;
        float a0 = o[dt][0] * inv0, a1 = o[dt][1] * inv0;
        float b0 = o[dt][2] * inv1, b1 = o[dt][3] * inv1;
        float a0h = __bfloat162float(__float2bfloat16(a0));
        float a1h = __bfloat162float(__float2bfloat16(a1));
        float b0h = __bfloat162float(__float2bfloat16(b0));
        float b1h = __bfloat162float(__float2bfloat16(b1));
        size_t r0b = ((size_t)kc * TT + row0) * 128;
        size_t r1b = ((size_t)kc * TT + row0 + 8) * 128;
        *(uint32_t*)((char*)Ahl + swzs(r0b + (size_t)cin * 2))      = pack_bf16x2(a0h, a1h);
        *(uint32_t*)((char*)Ahl + swzs(r0b + 64 + (size_t)cin * 2)) = pack_bf16x2(a0 - a0h, a1 - a1h);
        *(uint32_t*)((char*)Ahl + swzs(r1b + (size_t)cin * 2))      = pack_bf16x2(b0h, b1h);
        *(uint32_t*)((char*)Ahl + swzs(r1b + 64 + (size_t)cin * 2)) = pack_bf16x2(b0 - b0h, b1 - b1h);
    }
}

// ---------------------------------------------------------------------------
extern "C" void kernel_launch(void* const* d_in, const int* in_sizes, int n_in,
                              void* d_out, int out_size)
{
    const float* x    = (const float*)d_in[0];
    const float* wqkv = (const float*)d_in[1];
    const float* wout = (const float*)d_in[2];
    float* out = (float*)d_out;

    __nv_bfloat16 *xhl, *w1hl, *w2hl, *ahl, *qph, *qpl, *kvp;
    cudaGetSymbolAddress((void**)&xhl,  g_xhl);
    cudaGetSymbolAddress((void**)&w1hl, g_w1hl);
    cudaGetSymbolAddress((void**)&w2hl, g_w2hl);
    cudaGetSymbolAddress((void**)&ahl,  g_ahl);
    cudaGetSymbolAddress((void**)&qph,  g_qph);
    cudaGetSymbolAddress((void**)&qpl,  g_qpl);
    cudaGetSymbolAddress((void**)&kvp,  g_kvp);

    cudaFuncSetAttribute(tc_gemm,     cudaFuncAttributeMaxDynamicSharedMemorySize, GSMEM);
    cudaFuncSetAttribute(tc_gemm_qkv, cudaFuncAttributeMaxDynamicSharedMemorySize, GSMEM_QKV);
    cudaFuncSetAttribute(attn_mma,    cudaFuncAttributeMaxDynamicSharedMemorySize, ASMEM);

    // prep: single fused launch (x-split | w1T-split | w2T-split co-resident)
    prep_all<<<2048 + 3072 + 1024, 256>>>(x, wqkv, wout, xhl, w1hl, w2hl);

    // 1) QKV projection with fused attention-operand epilogue
    tc_gemm_qkv<<<dim3(3 * DD / 128, TT / 128), 256, GSMEM_QKV>>>(
        xhl, w1hl, qph, qpl, kvp, TT, 3 * DD, DD);

    // 2) causal attention (128-key tiles, 2-stage 64KB ring)
    attn_mma<<<dim3(TT / 128, NH), 256, ASMEM>>>(qph, qpl, kvp, ahl);

    // 3) output projection
    tc_gemm<<<dim3(DD / 128, TT / 128), 256, GSMEM>>>(ahl, w2hl, out, TT, DD, DD);
}